// round 9
// baseline (speedup 1.0000x reference)
#include <cuda_runtime.h>
#include <cuda_fp16.h>
#include <math.h>
#include <stdint.h>

// Problem constants
#define B_   32
#define F_   128
#define T_   4000
#define H_   256     // hidden
#define O_   512     // 4F
#define KDIM 256     // 2F
#define EPS  1e-6f

// Scan chunking: 32 chunks of 125 -> 4000
#define CHUNK 125
#define NC    32

// GEMM tiling
#define BM 128
#define BN 128
#define BK 32
#define ROWB 64                   // smem row stride bytes (XOR swizzle, no pad)
#define PL   (BM * ROWB)          // one plane: 8192 B
#define SSTR (2 * PL)             // one stage (A, B): 16384 B
#define NSTAGE 4
#define SMEM_GEMM (NSTAGE * SSTR) // 65536 B

// ---------------------------------------------------------------------------
// Scratch (device globals)
// ---------------------------------------------------------------------------
__device__ __align__(128) __half  g_Xf  [B_ * T_ * F_];   // fp16 [b][t][f] for GEMM1
__device__ __align__(128) __half  g_W1f [H_ * KDIM];
__device__ __align__(128) __half  g_W2f [O_ * KDIM];
__device__ __align__(128) __half  g_Hf  [B_ * T_ * H_];
__device__ __align__(128) __half  g_actH[B_ * T_ * O_];   // fp16 activations
__device__ float g_Ac[B_ * NC * F_];    // [b][c][f]
__device__ float g_Bc[B_ * NC * F_];
__device__ float g_Ms[B_ * NC * F_];

// ---------------------------------------------------------------------------
// Helpers
// ---------------------------------------------------------------------------
__device__ __forceinline__ uint32_t smem_u32(const void* p) {
    uint32_t a;
    asm("{ .reg .u64 t; cvta.to.shared.u64 t, %1; cvt.u32.u64 %0, t; }" : "=r"(a) : "l"(p));
    return a;
}
__device__ __forceinline__ void cp16(uint32_t dst, const void* src) {
    asm volatile("cp.async.cg.shared.global [%0], [%1], 16;" :: "r"(dst), "l"(src) : "memory");
}
#define CP_COMMIT() asm volatile("cp.async.commit_group;" ::: "memory")
#define CP_WAIT2()  asm volatile("cp.async.wait_group 2;" ::: "memory")

__device__ __forceinline__ void ldsm_x4(uint32_t& r0, uint32_t& r1, uint32_t& r2, uint32_t& r3,
                                        uint32_t addr) {
    asm volatile("ldmatrix.sync.aligned.m8n8.x4.shared.b16 {%0,%1,%2,%3}, [%4];"
                 : "=r"(r0), "=r"(r1), "=r"(r2), "=r"(r3) : "r"(addr));
}
__device__ __forceinline__ void mma_fp16(float* c, const uint32_t* a, const uint32_t* b) {
    asm volatile("mma.sync.aligned.m16n8k16.row.col.f32.f16.f16.f32 "
                 "{%0,%1,%2,%3}, {%4,%5,%6,%7}, {%8,%9}, {%0,%1,%2,%3};"
                 : "+f"(c[0]), "+f"(c[1]), "+f"(c[2]), "+f"(c[3])
                 : "r"(a[0]), "r"(a[1]), "r"(a[2]), "r"(a[3]), "r"(b[0]), "r"(b[1]));
}
__device__ __forceinline__ uint32_t pack_h2(float x, float y) {
    __half2 h = __floats2half2_rn(x, y);
    return *(uint32_t*)&h;
}

// ---------------------------------------------------------------------------
// Transpose + fp16 convert: in [R][C] fp32 -> out [C][R] fp16
// ---------------------------------------------------------------------------
__global__ void transpose_conv(const float* __restrict__ in, __half* __restrict__ outH,
                               int R, int C) {
    __shared__ float tile[32][33];
    size_t boff = (size_t)blockIdx.z * R * C;
    in += boff;
    int c0 = blockIdx.x * 32, r0 = blockIdx.y * 32;
    int x = threadIdx.x, y = threadIdx.y;
    #pragma unroll
    for (int i = 0; i < 32; i += 8)
        tile[y + i][x] = in[(size_t)(r0 + y + i) * C + c0 + x];
    __syncthreads();
    #pragma unroll
    for (int i = 0; i < 32; i += 8) {
        float v = tile[x][y + i];
        outH[boff + (size_t)(c0 + y + i) * R + r0 + x] = __float2half_rn(v);
    }
}

// ---------------------------------------------------------------------------
// GEMM via fp16 mma.sync, 4-stage cp.async pipeline, XOR-swizzled smem.
// MODE 1: Hf   = relu(concat(X[:,t-1],X[:,t]) @ W1 + b1)   [128000 x 256]
// MODE 2: actH = activation(h @ W2 + b2)                   [128000 x 512]
// ---------------------------------------------------------------------------
template<int MODE>
__global__ __launch_bounds__(256, 2) void gemm_mma(const float* __restrict__ bias) {
    extern __shared__ __align__(128) char sm[];
    const int tid = threadIdx.x;
    const int lane = tid & 31;
    const int wid = tid >> 5;
    const int wm = wid >> 2;
    const int wn = wid & 3;
    const int n0 = blockIdx.x * BN;
    const int m0 = blockIdx.y * BM;

    const uint32_t smbase = smem_u32(sm);

    // staging: thread -> (row0 + it*64, seg); swizzle const across both rows
    const int seg  = tid & 3;
    const int row0 = tid >> 2;
    const uint32_t sw_st = ((uint32_t)row0 >> 1) & 3;
    const uint32_t st_d0 = (uint32_t)row0 * ROWB + ((seg ^ sw_st) << 4);

    const __half* AF = (MODE == 1) ? g_Xf : g_Hf;
    const __half* WF = (MODE == 1) ? g_W1f : g_W2f;

    size_t acur[2], aprev[2], boff[2];
    #pragma unroll
    for (int it = 0; it < 2; it++) {
        int row = row0 + it * 64;
        if (MODE == 1) {
            int gr = m0 + row;
            int b = gr / T_;
            int t = gr - b * T_;
            int tp = t ? (t - 1) : 0;
            acur[it]  = ((size_t)b * T_ + t)  * F_ + seg * 8;
            aprev[it] = ((size_t)b * T_ + tp) * F_ + seg * 8;
        } else {
            acur[it] = (size_t)(m0 + row) * H_ + seg * 8;
        }
        boff[it] = (size_t)(n0 + row) * KDIM + seg * 8;
    }

    auto stage = [&](int c, int slot) {
        const int k0 = c * BK;
        uint32_t sA = smbase + slot * SSTR;
        #pragma unroll
        for (int it = 0; it < 2; it++) {
            uint32_t d = st_d0 + it * (64 * ROWB);
            size_t so;
            if (MODE == 1) so = (k0 < 128) ? (aprev[it] + k0) : (acur[it] + (k0 - 128));
            else           so = acur[it] + k0;
            cp16(sA + d,      AF + so);
            cp16(sA + PL + d, WF + boff[it] + k0);
        }
    };

    float acc[4][4][4];
    #pragma unroll
    for (int i = 0; i < 4; i++)
        #pragma unroll
        for (int j = 0; j < 4; j++)
            #pragma unroll
            for (int q = 0; q < 4; q++) acc[i][j][q] = 0.f;

    // ldmatrix addressing: swizzle const per thread (i*16/jj*16 preserve (row>>1)&3)
    const uint32_t a_rowb = (uint32_t)(wm * 64) + (lane & 15);
    const uint32_t sw_a   = (a_rowb >> 1) & 3;
    const uint32_t a_half = (uint32_t)lane >> 4;                 // 0/1
    const uint32_t b_rowb = (uint32_t)(wn * 32) + (((uint32_t)lane >> 4) << 3) + (lane & 7);
    const uint32_t sw_b   = (b_rowb >> 1) & 3;
    const uint32_t b_half = ((uint32_t)lane >> 3) & 1;

    stage(0, 0); CP_COMMIT();
    stage(1, 1); CP_COMMIT();
    stage(2, 2); CP_COMMIT();

    #pragma unroll 1
    for (int c = 0; c < KDIM / BK; c++) {
        CP_WAIT2();                  // group c complete (c+1, c+2 may be in flight)
        __syncthreads();             // all warps done reading slot (c-1)%4
        if (c + 3 < KDIM / BK) stage(c + 3, (c + 3) % NSTAGE);
        CP_COMMIT();

        const int slot = c % NSTAGE;
        const uint32_t sA = smbase + slot * SSTR;
        const uint32_t sB = sA + PL;

        #pragma unroll
        for (int s = 0; s < 2; s++) {
            const uint32_t a_co = ((2 * s + a_half) ^ sw_a) << 4;
            const uint32_t b_co = ((2 * s + b_half) ^ sw_b) << 4;
            uint32_t bf[4][2];
            #pragma unroll
            for (int jj = 0; jj < 2; jj++) {
                uint32_t off = (b_rowb + jj * 16) * ROWB + b_co;
                uint32_t r0, r1, r2, r3;
                ldsm_x4(r0, r1, r2, r3, sB + off);
                bf[2 * jj][0] = r0; bf[2 * jj][1] = r1;
                bf[2 * jj + 1][0] = r2; bf[2 * jj + 1][1] = r3;
            }
            #pragma unroll
            for (int i = 0; i < 4; i++) {
                uint32_t off = (a_rowb + i * 16) * ROWB + a_co;
                uint32_t af[4];
                ldsm_x4(af[0], af[1], af[2], af[3], sA + off);
                #pragma unroll
                for (int j = 0; j < 4; j++)
                    mma_fp16(acc[i][j], af, bf[j]);
            }
        }
    }

    // ---- epilogue ----
    const int rloc = lane >> 2;
    const int cpair = (lane & 3) * 2;
    #pragma unroll
    for (int i = 0; i < 4; i++) {
        int r0 = m0 + wm * 64 + i * 16 + rloc;
        int r1 = r0 + 8;
        #pragma unroll
        for (int j = 0; j < 4; j++) {
            int ng = n0 + wn * 32 + j * 8 + cpair;
            float2 bb = *(const float2*)&bias[ng];
            float u0 = acc[i][j][0] + bb.x, u1 = acc[i][j][1] + bb.y;
            float u2 = acc[i][j][2] + bb.x, u3 = acc[i][j][3] + bb.y;
            if (MODE == 1) {
                u0 = fmaxf(u0, 0.f); u1 = fmaxf(u1, 0.f);
                u2 = fmaxf(u2, 0.f); u3 = fmaxf(u3, 0.f);
                *(uint32_t*)&g_Hf[(size_t)r0 * H_ + ng] = pack_h2(u0, u1);
                *(uint32_t*)&g_Hf[(size_t)r1 * H_ + ng] = pack_h2(u2, u3);
            } else {
                bool sp = (blockIdx.x == 2);   // cols [256,384): softplus (delta)
                float uu[4] = {u0, u1, u2, u3};
                float v[4];
                #pragma unroll
                for (int q = 0; q < 4; q++) {
                    float u = uu[q];
                    v[q] = sp ? (__logf(1.f + __expf(-fabsf(u))) + fmaxf(u, 0.f))
                              : (1.f / (1.f + __expf(-u)));
                }
                *(uint32_t*)&g_actH[(size_t)r0 * O_ + ng] = pack_h2(v[0], v[1]);
                *(uint32_t*)&g_actH[(size_t)r1 * O_ + ng] = pack_h2(v[2], v[3]);
            }
        }
    }
}

// ---------------------------------------------------------------------------
// Scan stage A: per-chunk composition  (writes [b][c][f], fully coalesced)
// X read in its native [b][f][t] layout (t-sequential per lane; L1 reuse 31/32)
// ---------------------------------------------------------------------------
__global__ __launch_bounds__(256) void scan_reduce_kernel(const float* __restrict__ X) {
    int id = blockIdx.x * blockDim.x + threadIdx.x;
    int f = id & (F_ - 1);
    int c = (id >> 7) & (NC - 1);
    int b = id >> 12;

    const __half* actb = g_actH + (size_t)(b * T_) * O_;
    const float*  Xr   = X + (size_t)(b * F_ + f) * T_;

    float A = 1.f, Bv = 0.f;
    int t0 = c * CHUNK;
    for (int t = t0; t < t0 + CHUNK; t++) {
        float s = __half2float(actb[(size_t)t * O_ + f]);
        float x = Xr[t];
        float a = 1.f - s;
        A  *= a;
        Bv = a * Bv + s * x;
    }
    g_Ac[id] = A;
    g_Bc[id] = Bv;
}

// ---------------------------------------------------------------------------
// Scan stage B: per-(b,f) chain over NC chunk summaries (coalesced over f)
// ---------------------------------------------------------------------------
__global__ __launch_bounds__(128) void scan_chain_kernel() {
    int b = blockIdx.x, f = threadIdx.x;
    float M = 0.f;
    #pragma unroll
    for (int c = 0; c < NC; c++) {
        int idx = (b * NC + c) * F_ + f;
        g_Ms[idx] = M;
        M = g_Ac[idx] * M + g_Bc[idx];
    }
}

// ---------------------------------------------------------------------------
// Scan stage C: replay + PCEN epilogue; smem transpose for coalesced output
// block = (b*NC + c), 128 threads = f
// ---------------------------------------------------------------------------
__global__ __launch_bounds__(128) void scan_final_kernel(const float* __restrict__ X,
                                                         float* __restrict__ out) {
    __shared__ float tile[32][129];
    int bc = blockIdx.x;
    int b = bc >> 5;           // /NC
    int c = bc & (NC - 1);
    int f = threadIdx.x;
    int lane = f & 31, wid = f >> 5;

    const __half* actb = g_actH + (size_t)(b * T_) * O_;
    const float*  Xr   = X + (size_t)(b * F_ + f) * T_;

    float M = g_Ms[bc * F_ + f];
    int t0 = c * CHUNK, t1 = t0 + CHUNK;
    for (int tb = t0; tb < t1; tb += 32) {
        int nrow = min(32, t1 - tb);
        for (int q = 0; q < nrow; q++) {
            int t = tb + q;
            const __half* rowp = actb + (size_t)t * O_;
            float s     = __half2float(rowp[f]);
            float alpha = __half2float(rowp[128 + f]);
            float delta = __half2float(rowp[256 + f]);
            float r     = __half2float(rowp[384 + f]);
            float x = Xr[t];
            M = (1.f - s) * M + s * x;
            float base = x * __powf(M + EPS, -alpha) + delta;
            tile[q][f] = __powf(base, r) - __powf(delta, r);
        }
        __syncthreads();
        #pragma unroll
        for (int ff = wid; ff < 128; ff += 4) {
            if (lane < nrow)
                out[(size_t)(b * F_ + ff) * T_ + tb + lane] = tile[lane][ff];
        }
        __syncthreads();
    }
}

// ---------------------------------------------------------------------------
// Launch
// ---------------------------------------------------------------------------
extern "C" void kernel_launch(void* const* d_in, const int* in_sizes, int n_in,
                              void* d_out, int out_size) {
    const float* X  = (const float*)d_in[0];
    const float* W1 = (const float*)d_in[1];
    const float* b1 = (const float*)d_in[2];
    const float* W2 = (const float*)d_in[3];
    const float* b2 = (const float*)d_in[4];
    float* out = (float*)d_out;

    __half *Xf, *W1f, *W2f;
    cudaGetSymbolAddress((void**)&Xf,  g_Xf);
    cudaGetSymbolAddress((void**)&W1f, g_W1f);
    cudaGetSymbolAddress((void**)&W2f, g_W2f);

    // Idempotent host-side attribute set (no stream interaction; capture-safe)
    cudaFuncSetAttribute(gemm_mma<1>, cudaFuncAttributeMaxDynamicSharedMemorySize, SMEM_GEMM);
    cudaFuncSetAttribute(gemm_mma<2>, cudaFuncAttributeMaxDynamicSharedMemorySize, SMEM_GEMM);

    // X [F][T] per batch -> Xf [T][F]; W1 [K][H] -> [H][K]; W2 [K][O] -> [O][K]
    transpose_conv<<<dim3(T_ / 32, F_ / 32, B_), dim3(32, 8)>>>(X, Xf, F_, T_);
    transpose_conv<<<dim3(H_ / 32, KDIM / 32, 1), dim3(32, 8)>>>(W1, W1f, KDIM, H_);
    transpose_conv<<<dim3(O_ / 32, KDIM / 32, 1), dim3(32, 8)>>>(W2, W2f, KDIM, O_);

    gemm_mma<1><<<dim3(H_ / BN, (B_ * T_) / BM), 256, SMEM_GEMM>>>(b1);   // (2, 1000)
    gemm_mma<2><<<dim3(O_ / BN, (B_ * T_) / BM), 256, SMEM_GEMM>>>(b2);   // (4, 1000)

    scan_reduce_kernel<<<(B_ * F_ * NC) / 256, 256>>>(X);
    scan_chain_kernel<<<B_, 128>>>();
    scan_final_kernel<<<B_ * NC, 128>>>(X, out);
}

// round 10
// speedup vs baseline: 1.1512x; 1.1512x over previous
#include <cuda_runtime.h>
#include <cuda_fp16.h>
#include <math.h>
#include <stdint.h>

// Problem constants
#define B_   32
#define F_   128
#define T_   4000
#define H_   256     // hidden
#define O_   512     // 4F
#define KDIM 256     // 2F
#define EPS  1e-6f

// Scan chunking: 32 chunks of 125 -> 4000
#define CHUNK 125
#define NC    32

// GEMM tiling
#define BM 128
#define BN 128
#define BK 32
#define ROWB 64                   // smem row stride bytes (XOR swizzle, no pad)
#define PL   (BM * ROWB)          // one plane: 8192 B
#define SSTR (2 * PL)             // one stage (A, B): 16384 B
#define NSTAGE 4
#define SMEM_GEMM (NSTAGE * SSTR) // 65536 B

// ---------------------------------------------------------------------------
// Scratch (device globals)
// ---------------------------------------------------------------------------
__device__ __align__(128) float   g_Xt  [B_ * T_ * F_];   // fp32 [b][t][f] for scans
__device__ __align__(128) __half  g_Xf  [B_ * T_ * F_];   // fp16 [b][t][f] for GEMM1
__device__ __align__(128) __half  g_W1f [H_ * KDIM];
__device__ __align__(128) __half  g_W2f [O_ * KDIM];
__device__ __align__(128) __half  g_Hf  [B_ * T_ * H_];
__device__ __align__(128) __half  g_actH[B_ * T_ * O_];   // fp16 activations
__device__ float g_Ac[B_ * NC * F_];    // [b][c][f]
__device__ float g_Bc[B_ * NC * F_];
__device__ float g_Ms[B_ * NC * F_];

// ---------------------------------------------------------------------------
// Helpers
// ---------------------------------------------------------------------------
__device__ __forceinline__ uint32_t smem_u32(const void* p) {
    uint32_t a;
    asm("{ .reg .u64 t; cvta.to.shared.u64 t, %1; cvt.u32.u64 %0, t; }" : "=r"(a) : "l"(p));
    return a;
}
__device__ __forceinline__ void cp16(uint32_t dst, const void* src) {
    asm volatile("cp.async.cg.shared.global [%0], [%1], 16;" :: "r"(dst), "l"(src) : "memory");
}
#define CP_COMMIT() asm volatile("cp.async.commit_group;" ::: "memory")
#define CP_WAIT2()  asm volatile("cp.async.wait_group 2;" ::: "memory")

__device__ __forceinline__ void ldsm_x4(uint32_t& r0, uint32_t& r1, uint32_t& r2, uint32_t& r3,
                                        uint32_t addr) {
    asm volatile("ldmatrix.sync.aligned.m8n8.x4.shared.b16 {%0,%1,%2,%3}, [%4];"
                 : "=r"(r0), "=r"(r1), "=r"(r2), "=r"(r3) : "r"(addr));
}
__device__ __forceinline__ void mma_fp16(float* c, const uint32_t* a, const uint32_t* b) {
    asm volatile("mma.sync.aligned.m16n8k16.row.col.f32.f16.f16.f32 "
                 "{%0,%1,%2,%3}, {%4,%5,%6,%7}, {%8,%9}, {%0,%1,%2,%3};"
                 : "+f"(c[0]), "+f"(c[1]), "+f"(c[2]), "+f"(c[3])
                 : "r"(a[0]), "r"(a[1]), "r"(a[2]), "r"(a[3]), "r"(b[0]), "r"(b[1]));
}
__device__ __forceinline__ uint32_t pack_h2(float x, float y) {
    __half2 h = __floats2half2_rn(x, y);
    return *(uint32_t*)&h;
}

// ---------------------------------------------------------------------------
// Transpose + fp16 convert: in [R][C] fp32 -> out [C][R] (fp32 optional, fp16)
// ---------------------------------------------------------------------------
__global__ void transpose_conv(const float* __restrict__ in, float* __restrict__ outF,
                               __half* __restrict__ outH, int R, int C) {
    __shared__ float tile[32][33];
    size_t boff = (size_t)blockIdx.z * R * C;
    in += boff;
    int c0 = blockIdx.x * 32, r0 = blockIdx.y * 32;
    int x = threadIdx.x, y = threadIdx.y;
    #pragma unroll
    for (int i = 0; i < 32; i += 8)
        tile[y + i][x] = in[(size_t)(r0 + y + i) * C + c0 + x];
    __syncthreads();
    #pragma unroll
    for (int i = 0; i < 32; i += 8) {
        float v = tile[x][y + i];
        size_t idx = boff + (size_t)(c0 + y + i) * R + r0 + x;
        if (outF) outF[idx] = v;
        outH[idx] = __float2half_rn(v);
    }
}

// ---------------------------------------------------------------------------
// GEMM via fp16 mma.sync, 4-stage cp.async pipeline, XOR-swizzled smem.
// MODE 1: Hf   = relu(concat(X[:,t-1],X[:,t]) @ W1 + b1)   [128000 x 256]
// MODE 2: actH = activation(h @ W2 + b2)                   [128000 x 512]
// ---------------------------------------------------------------------------
template<int MODE>
__global__ __launch_bounds__(256, 2) void gemm_mma(const float* __restrict__ bias) {
    extern __shared__ __align__(128) char sm[];
    const int tid = threadIdx.x;
    const int lane = tid & 31;
    const int wid = tid >> 5;
    const int wm = wid >> 2;
    const int wn = wid & 3;
    const int n0 = blockIdx.x * BN;
    const int m0 = blockIdx.y * BM;

    const uint32_t smbase = smem_u32(sm);

    // staging: thread -> (row0 + it*64, seg); swizzle const across both rows
    const int seg  = tid & 3;
    const int row0 = tid >> 2;
    const uint32_t sw_st = ((uint32_t)row0 >> 1) & 3;
    const uint32_t st_d0 = (uint32_t)row0 * ROWB + ((seg ^ sw_st) << 4);

    const __half* AF = (MODE == 1) ? g_Xf : g_Hf;
    const __half* WF = (MODE == 1) ? g_W1f : g_W2f;

    size_t acur[2], aprev[2], boff[2];
    #pragma unroll
    for (int it = 0; it < 2; it++) {
        int row = row0 + it * 64;
        if (MODE == 1) {
            int gr = m0 + row;
            int b = gr / T_;
            int t = gr - b * T_;
            int tp = t ? (t - 1) : 0;
            acur[it]  = ((size_t)b * T_ + t)  * F_ + seg * 8;
            aprev[it] = ((size_t)b * T_ + tp) * F_ + seg * 8;
        } else {
            acur[it] = (size_t)(m0 + row) * H_ + seg * 8;
        }
        boff[it] = (size_t)(n0 + row) * KDIM + seg * 8;
    }

    auto stage = [&](int c, int slot) {
        const int k0 = c * BK;
        uint32_t sA = smbase + slot * SSTR;
        #pragma unroll
        for (int it = 0; it < 2; it++) {
            uint32_t d = st_d0 + it * (64 * ROWB);
            size_t so;
            if (MODE == 1) so = (k0 < 128) ? (aprev[it] + k0) : (acur[it] + (k0 - 128));
            else           so = acur[it] + k0;
            cp16(sA + d,      AF + so);
            cp16(sA + PL + d, WF + boff[it] + k0);
        }
    };

    float acc[4][4][4];
    #pragma unroll
    for (int i = 0; i < 4; i++)
        #pragma unroll
        for (int j = 0; j < 4; j++)
            #pragma unroll
            for (int q = 0; q < 4; q++) acc[i][j][q] = 0.f;

    // ldmatrix addressing: swizzle const per thread (i*16/jj*16 preserve (row>>1)&3)
    const uint32_t a_rowb = (uint32_t)(wm * 64) + (lane & 15);
    const uint32_t sw_a   = (a_rowb >> 1) & 3;
    const uint32_t a_half = (uint32_t)lane >> 4;                 // 0/1
    const uint32_t b_rowb = (uint32_t)(wn * 32) + (((uint32_t)lane >> 4) << 3) + (lane & 7);
    const uint32_t sw_b   = (b_rowb >> 1) & 3;
    const uint32_t b_half = ((uint32_t)lane >> 3) & 1;

    stage(0, 0); CP_COMMIT();
    stage(1, 1); CP_COMMIT();
    stage(2, 2); CP_COMMIT();

    #pragma unroll 1
    for (int c = 0; c < KDIM / BK; c++) {
        CP_WAIT2();                  // group c complete (c+1, c+2 may be in flight)
        __syncthreads();             // all warps done reading slot (c-1)%4
        if (c + 3 < KDIM / BK) stage(c + 3, (c + 3) % NSTAGE);
        CP_COMMIT();

        const int slot = c % NSTAGE;
        const uint32_t sA = smbase + slot * SSTR;
        const uint32_t sB = sA + PL;

        #pragma unroll
        for (int s = 0; s < 2; s++) {
            const uint32_t a_co = ((2 * s + a_half) ^ sw_a) << 4;
            const uint32_t b_co = ((2 * s + b_half) ^ sw_b) << 4;
            uint32_t bf[4][2];
            #pragma unroll
            for (int jj = 0; jj < 2; jj++) {
                uint32_t off = (b_rowb + jj * 16) * ROWB + b_co;
                uint32_t r0, r1, r2, r3;
                ldsm_x4(r0, r1, r2, r3, sB + off);
                bf[2 * jj][0] = r0; bf[2 * jj][1] = r1;
                bf[2 * jj + 1][0] = r2; bf[2 * jj + 1][1] = r3;
            }
            #pragma unroll
            for (int i = 0; i < 4; i++) {
                uint32_t off = (a_rowb + i * 16) * ROWB + a_co;
                uint32_t af[4];
                ldsm_x4(af[0], af[1], af[2], af[3], sA + off);
                #pragma unroll
                for (int j = 0; j < 4; j++)
                    mma_fp16(acc[i][j], af, bf[j]);
            }
        }
    }

    // ---- epilogue ----
    const int rloc = lane >> 2;
    const int cpair = (lane & 3) * 2;
    #pragma unroll
    for (int i = 0; i < 4; i++) {
        int r0 = m0 + wm * 64 + i * 16 + rloc;
        int r1 = r0 + 8;
        #pragma unroll
        for (int j = 0; j < 4; j++) {
            int ng = n0 + wn * 32 + j * 8 + cpair;
            float2 bb = *(const float2*)&bias[ng];
            float u0 = acc[i][j][0] + bb.x, u1 = acc[i][j][1] + bb.y;
            float u2 = acc[i][j][2] + bb.x, u3 = acc[i][j][3] + bb.y;
            if (MODE == 1) {
                u0 = fmaxf(u0, 0.f); u1 = fmaxf(u1, 0.f);
                u2 = fmaxf(u2, 0.f); u3 = fmaxf(u3, 0.f);
                *(uint32_t*)&g_Hf[(size_t)r0 * H_ + ng] = pack_h2(u0, u1);
                *(uint32_t*)&g_Hf[(size_t)r1 * H_ + ng] = pack_h2(u2, u3);
            } else {
                bool sp = (blockIdx.x == 2);   // cols [256,384): softplus (delta)
                float uu[4] = {u0, u1, u2, u3};
                float v[4];
                #pragma unroll
                for (int q = 0; q < 4; q++) {
                    float u = uu[q];
                    v[q] = sp ? (__logf(1.f + __expf(-fabsf(u))) + fmaxf(u, 0.f))
                              : (1.f / (1.f + __expf(-u)));
                }
                *(uint32_t*)&g_actH[(size_t)r0 * O_ + ng] = pack_h2(v[0], v[1]);
                *(uint32_t*)&g_actH[(size_t)r1 * O_ + ng] = pack_h2(v[2], v[3]);
            }
        }
    }
}

// ---------------------------------------------------------------------------
// Scan stage A: per-chunk composition  (writes [b][c][f], fully coalesced)
// ---------------------------------------------------------------------------
__global__ __launch_bounds__(256) void scan_reduce_kernel() {
    int id = blockIdx.x * blockDim.x + threadIdx.x;
    int f = id & (F_ - 1);
    int c = (id >> 7) & (NC - 1);
    int b = id >> 12;

    const __half* actb = g_actH + (size_t)(b * T_) * O_;
    const float*  Xtb  = g_Xt + (size_t)b * T_ * F_;

    float A = 1.f, Bv = 0.f;
    int t0 = c * CHUNK;
    for (int t = t0; t < t0 + CHUNK; t++) {
        float s = __half2float(actb[(size_t)t * O_ + f]);
        float x = Xtb[(size_t)t * F_ + f];
        float a = 1.f - s;
        A  *= a;
        Bv = a * Bv + s * x;
    }
    g_Ac[id] = A;
    g_Bc[id] = Bv;
}

// ---------------------------------------------------------------------------
// Scan stage B: per-(b,f) chain over NC chunk summaries (coalesced over f)
// ---------------------------------------------------------------------------
__global__ __launch_bounds__(128) void scan_chain_kernel() {
    int b = blockIdx.x, f = threadIdx.x;
    float M = 0.f;
    #pragma unroll
    for (int c = 0; c < NC; c++) {
        int idx = (b * NC + c) * F_ + f;
        g_Ms[idx] = M;
        M = g_Ac[idx] * M + g_Bc[idx];
    }
}

// ---------------------------------------------------------------------------
// Scan stage C: replay + PCEN epilogue; smem transpose for coalesced output
// block = (b*NC + c), 128 threads = f
// ---------------------------------------------------------------------------
__global__ __launch_bounds__(128) void scan_final_kernel(float* __restrict__ out) {
    __shared__ float tile[32][129];
    int bc = blockIdx.x;
    int b = bc >> 5;           // /NC
    int c = bc & (NC - 1);
    int f = threadIdx.x;
    int lane = f & 31, wid = f >> 5;

    const __half* actb = g_actH + (size_t)(b * T_) * O_;
    const float*  Xtb  = g_Xt + (size_t)b * T_ * F_;

    float M = g_Ms[bc * F_ + f];
    int t0 = c * CHUNK, t1 = t0 + CHUNK;
    for (int tb = t0; tb < t1; tb += 32) {
        int nrow = min(32, t1 - tb);
        for (int q = 0; q < nrow; q++) {
            int t = tb + q;
            const __half* rowp = actb + (size_t)t * O_;
            float s     = __half2float(rowp[f]);
            float alpha = __half2float(rowp[128 + f]);
            float delta = __half2float(rowp[256 + f]);
            float r     = __half2float(rowp[384 + f]);
            float x = Xtb[(size_t)t * F_ + f];
            M = (1.f - s) * M + s * x;
            float base = x * __powf(M + EPS, -alpha) + delta;
            tile[q][f] = __powf(base, r) - __powf(delta, r);
        }
        __syncthreads();
        #pragma unroll
        for (int ff = wid; ff < 128; ff += 4) {
            if (lane < nrow)
                out[(size_t)(b * F_ + ff) * T_ + tb + lane] = tile[lane][ff];
        }
        __syncthreads();
    }
}

// ---------------------------------------------------------------------------
// Launch
// ---------------------------------------------------------------------------
extern "C" void kernel_launch(void* const* d_in, const int* in_sizes, int n_in,
                              void* d_out, int out_size) {
    const float* X  = (const float*)d_in[0];
    const float* W1 = (const float*)d_in[1];
    const float* b1 = (const float*)d_in[2];
    const float* W2 = (const float*)d_in[3];
    const float* b2 = (const float*)d_in[4];
    float* out = (float*)d_out;

    float *Xt;
    __half *Xf, *W1f, *W2f;
    cudaGetSymbolAddress((void**)&Xt,  g_Xt);
    cudaGetSymbolAddress((void**)&Xf,  g_Xf);
    cudaGetSymbolAddress((void**)&W1f, g_W1f);
    cudaGetSymbolAddress((void**)&W2f, g_W2f);

    // Idempotent host-side attribute set (no stream interaction; capture-safe)
    cudaFuncSetAttribute(gemm_mma<1>, cudaFuncAttributeMaxDynamicSharedMemorySize, SMEM_GEMM);
    cudaFuncSetAttribute(gemm_mma<2>, cudaFuncAttributeMaxDynamicSharedMemorySize, SMEM_GEMM);

    // X [F][T] per batch -> Xt(fp32)+Xf(fp16) [T][F]; W1 -> [H][K]; W2 -> [O][K]
    transpose_conv<<<dim3(T_ / 32, F_ / 32, B_), dim3(32, 8)>>>(X, Xt, Xf, F_, T_);
    transpose_conv<<<dim3(H_ / 32, KDIM / 32, 1), dim3(32, 8)>>>(W1, nullptr, W1f, KDIM, H_);
    transpose_conv<<<dim3(O_ / 32, KDIM / 32, 1), dim3(32, 8)>>>(W2, nullptr, W2f, KDIM, O_);

    gemm_mma<1><<<dim3(H_ / BN, (B_ * T_) / BM), 256, SMEM_GEMM>>>(b1);   // (2, 1000)
    gemm_mma<2><<<dim3(O_ / BN, (B_ * T_) / BM), 256, SMEM_GEMM>>>(b2);   // (4, 1000)

    scan_reduce_kernel<<<(B_ * F_ * NC) / 256, 256>>>();
    scan_chain_kernel<<<B_, 128>>>();
    scan_final_kernel<<<B_ * NC, 128>>>(out);
}

// round 11
// speedup vs baseline: 1.2098x; 1.0509x over previous
#include <cuda_runtime.h>
#include <cuda_fp16.h>
#include <math.h>
#include <stdint.h>

// Problem constants
#define B_   32
#define F_   128
#define T_   4000
#define H_   256     // hidden
#define O_   512     // 4F
#define KDIM 256     // 2F
#define EPS  1e-6f

// Scan chunking: 32 chunks of 125 -> 4000
#define CHUNK 125
#define NC    32

// GEMM tiling
#define BM 128
#define BN 128
#define BK 64
#define ROWB 128                  // smem row stride bytes (8x16B chunks, XOR swizzle)
#define PL   (BM * ROWB)          // one plane: 16384 B
#define SSTR (2 * PL)             // one stage (A, B): 32768 B
#define NSTAGE 3
#define SMEM_GEMM (NSTAGE * SSTR) // 98304 B
#define NKC (KDIM / BK)           // 4 K-chunks

// ---------------------------------------------------------------------------
// Scratch (device globals)
// ---------------------------------------------------------------------------
__device__ __align__(128) float   g_Xt  [B_ * T_ * F_];   // fp32 [b][t][f] for scans
__device__ __align__(128) __half  g_Xf  [B_ * T_ * F_];   // fp16 [b][t][f] for GEMM1
__device__ __align__(128) __half  g_W1f [H_ * KDIM];
__device__ __align__(128) __half  g_W2f [O_ * KDIM];
__device__ __align__(128) __half  g_Hf  [B_ * T_ * H_];
__device__ __align__(128) __half  g_actH[B_ * T_ * O_];   // fp16 activations
__device__ float g_Ac[B_ * NC * F_];    // [b][c][f]
__device__ float g_Bc[B_ * NC * F_];
__device__ float g_Ms[B_ * NC * F_];

// ---------------------------------------------------------------------------
// Helpers
// ---------------------------------------------------------------------------
__device__ __forceinline__ uint32_t smem_u32(const void* p) {
    uint32_t a;
    asm("{ .reg .u64 t; cvta.to.shared.u64 t, %1; cvt.u32.u64 %0, t; }" : "=r"(a) : "l"(p));
    return a;
}
__device__ __forceinline__ void cp16(uint32_t dst, const void* src) {
    asm volatile("cp.async.cg.shared.global [%0], [%1], 16;" :: "r"(dst), "l"(src) : "memory");
}
#define CP_COMMIT() asm volatile("cp.async.commit_group;" ::: "memory")
#define CP_WAIT1()  asm volatile("cp.async.wait_group 1;" ::: "memory")

__device__ __forceinline__ void ldsm_x4(uint32_t& r0, uint32_t& r1, uint32_t& r2, uint32_t& r3,
                                        uint32_t addr) {
    asm volatile("ldmatrix.sync.aligned.m8n8.x4.shared.b16 {%0,%1,%2,%3}, [%4];"
                 : "=r"(r0), "=r"(r1), "=r"(r2), "=r"(r3) : "r"(addr));
}
__device__ __forceinline__ void mma_fp16(float* c, const uint32_t* a, const uint32_t* b) {
    asm volatile("mma.sync.aligned.m16n8k16.row.col.f32.f16.f16.f32 "
                 "{%0,%1,%2,%3}, {%4,%5,%6,%7}, {%8,%9}, {%0,%1,%2,%3};"
                 : "+f"(c[0]), "+f"(c[1]), "+f"(c[2]), "+f"(c[3])
                 : "r"(a[0]), "r"(a[1]), "r"(a[2]), "r"(a[3]), "r"(b[0]), "r"(b[1]));
}
__device__ __forceinline__ uint32_t pack_h2(float x, float y) {
    __half2 h = __floats2half2_rn(x, y);
    return *(uint32_t*)&h;
}

// ---------------------------------------------------------------------------
// Transpose + fp16 convert: in [R][C] fp32 -> out [C][R] (fp32 optional, fp16)
// ---------------------------------------------------------------------------
__global__ void transpose_conv(const float* __restrict__ in, float* __restrict__ outF,
                               __half* __restrict__ outH, int R, int C) {
    __shared__ float tile[32][33];
    size_t boff = (size_t)blockIdx.z * R * C;
    in += boff;
    int c0 = blockIdx.x * 32, r0 = blockIdx.y * 32;
    int x = threadIdx.x, y = threadIdx.y;
    #pragma unroll
    for (int i = 0; i < 32; i += 8)
        tile[y + i][x] = in[(size_t)(r0 + y + i) * C + c0 + x];
    __syncthreads();
    #pragma unroll
    for (int i = 0; i < 32; i += 8) {
        float v = tile[x][y + i];
        size_t idx = boff + (size_t)(c0 + y + i) * R + r0 + x;
        if (outF) outF[idx] = v;
        outH[idx] = __float2half_rn(v);
    }
}

// ---------------------------------------------------------------------------
// GEMM via fp16 mma.sync, BK=64, 3-stage cp.async pipeline, XOR-swizzled smem.
// MODE 1: Hf   = relu(concat(X[:,t-1],X[:,t]) @ W1 + b1)   [128000 x 256]
// MODE 2: actH = activation(h @ W2 + b2)                   [128000 x 512]
// ---------------------------------------------------------------------------
template<int MODE>
__global__ __launch_bounds__(256, 2) void gemm_mma(const float* __restrict__ bias) {
    extern __shared__ __align__(128) char sm[];
    const int tid = threadIdx.x;
    const int lane = tid & 31;
    const int wid = tid >> 5;
    const int wm = wid >> 2;
    const int wn = wid & 3;
    const int n0 = blockIdx.x * BN;
    const int m0 = blockIdx.y * BM;

    const uint32_t smbase = smem_u32(sm);

    // staging: thread item p -> row = (tid>>3) + 32p, chunk k = tid&7
    // (row&7) == (tid>>3)&7 for all p -> swizzle const per thread
    const int st_row = tid >> 3;            // 0..31
    const int st_k   = tid & 7;             // 16B chunk in row
    const uint32_t st_sw = (uint32_t)(st_row & 7);
    const uint32_t st_d0 = (uint32_t)st_row * ROWB + (((uint32_t)st_k ^ st_sw) << 4);

    const __half* AF = (MODE == 1) ? g_Xf : g_Hf;
    const __half* WF = (MODE == 1) ? g_W1f : g_W2f;

    size_t acur[4], aprev[4], boff[4];
    #pragma unroll
    for (int p = 0; p < 4; p++) {
        int row = st_row + 32 * p;
        if (MODE == 1) {
            int gr = m0 + row;
            int b = gr / T_;
            int t = gr - b * T_;
            int tp = t ? (t - 1) : 0;
            acur[p]  = ((size_t)b * T_ + t)  * F_ + st_k * 8;
            aprev[p] = ((size_t)b * T_ + tp) * F_ + st_k * 8;
        } else {
            acur[p] = (size_t)(m0 + row) * H_ + st_k * 8;
        }
        boff[p] = (size_t)(n0 + row) * KDIM + st_k * 8;
    }

    auto stage = [&](int c, int slot) {
        const int k0 = c * BK;
        uint32_t sA = smbase + slot * SSTR;
        #pragma unroll
        for (int p = 0; p < 4; p++) {
            uint32_t d = st_d0 + p * (32 * ROWB);
            size_t so;
            if (MODE == 1) so = (k0 < 128) ? (aprev[p] + k0) : (acur[p] + (k0 - 128));
            else           so = acur[p] + k0;
            cp16(sA + d,      AF + so);
            cp16(sA + PL + d, WF + boff[p] + k0);
        }
    };

    float acc[4][4][4];
    #pragma unroll
    for (int i = 0; i < 4; i++)
        #pragma unroll
        for (int j = 0; j < 4; j++)
            #pragma unroll
            for (int q = 0; q < 4; q++) acc[i][j][q] = 0.f;

    // ldmatrix addressing: all row offsets (i*16, jj*16, wn*32, 8*(lane>>4)) are
    // multiples of 8 -> (row&7) == (lane&7) for both A and B
    const uint32_t a_rowb = (uint32_t)(wm * 64) + (lane & 15);
    const uint32_t a_half = (uint32_t)lane >> 4;                 // 0/1
    const uint32_t b_rowb = (uint32_t)(wn * 32) + (((uint32_t)lane >> 4) << 3) + (lane & 7);
    const uint32_t b_half = ((uint32_t)lane >> 3) & 1;
    const uint32_t sw_ln  = (uint32_t)lane & 7;
    const uint32_t sw_a   = a_rowb & 7;
    const uint32_t sw_b   = b_rowb & 7;

    stage(0, 0); CP_COMMIT();
    stage(1, 1); CP_COMMIT();

    #pragma unroll 1
    for (int c = 0; c < NKC; c++) {
        CP_WAIT1();                  // group c complete (c+1 may be in flight)
        __syncthreads();             // all warps done reading slot (c-1)%3
        if (c + 2 < NKC) stage(c + 2, (c + 2) % NSTAGE);
        CP_COMMIT();

        const int slot = c % NSTAGE;
        const uint32_t sA = smbase + slot * SSTR;
        const uint32_t sB = sA + PL;

        #pragma unroll
        for (int s = 0; s < 4; s++) {
            const uint32_t a_co = ((2 * s + a_half) ^ sw_a) << 4;
            const uint32_t b_co = ((2 * s + b_half) ^ sw_b) << 4;
            uint32_t bf[4][2];
            #pragma unroll
            for (int jj = 0; jj < 2; jj++) {
                uint32_t off = (b_rowb + jj * 16) * ROWB + b_co;
                uint32_t r0, r1, r2, r3;
                ldsm_x4(r0, r1, r2, r3, sB + off);
                bf[2 * jj][0] = r0; bf[2 * jj][1] = r1;
                bf[2 * jj + 1][0] = r2; bf[2 * jj + 1][1] = r3;
            }
            #pragma unroll
            for (int i = 0; i < 4; i++) {
                uint32_t off = (a_rowb + i * 16) * ROWB + a_co;
                uint32_t af[4];
                ldsm_x4(af[0], af[1], af[2], af[3], sA + off);
                #pragma unroll
                for (int j = 0; j < 4; j++)
                    mma_fp16(acc[i][j], af, bf[j]);
            }
        }
    }

    // ---- epilogue ----
    const int rloc = lane >> 2;
    const int cpair = (lane & 3) * 2;
    #pragma unroll
    for (int i = 0; i < 4; i++) {
        int r0 = m0 + wm * 64 + i * 16 + rloc;
        int r1 = r0 + 8;
        #pragma unroll
        for (int j = 0; j < 4; j++) {
            int ng = n0 + wn * 32 + j * 8 + cpair;
            float2 bb = *(const float2*)&bias[ng];
            float u0 = acc[i][j][0] + bb.x, u1 = acc[i][j][1] + bb.y;
            float u2 = acc[i][j][2] + bb.x, u3 = acc[i][j][3] + bb.y;
            if (MODE == 1) {
                u0 = fmaxf(u0, 0.f); u1 = fmaxf(u1, 0.f);
                u2 = fmaxf(u2, 0.f); u3 = fmaxf(u3, 0.f);
                *(uint32_t*)&g_Hf[(size_t)r0 * H_ + ng] = pack_h2(u0, u1);
                *(uint32_t*)&g_Hf[(size_t)r1 * H_ + ng] = pack_h2(u2, u3);
            } else {
                bool sp = (blockIdx.x == 2);   // cols [256,384): softplus (delta)
                float uu[4] = {u0, u1, u2, u3};
                float v[4];
                #pragma unroll
                for (int q = 0; q < 4; q++) {
                    float u = uu[q];
                    v[q] = sp ? (__logf(1.f + __expf(-fabsf(u))) + fmaxf(u, 0.f))
                              : (1.f / (1.f + __expf(-u)));
                }
                *(uint32_t*)&g_actH[(size_t)r0 * O_ + ng] = pack_h2(v[0], v[1]);
                *(uint32_t*)&g_actH[(size_t)r1 * O_ + ng] = pack_h2(v[2], v[3]);
            }
        }
    }
}

// ---------------------------------------------------------------------------
// Scan stage A: per-chunk composition  (writes [b][c][f], fully coalesced)
// ---------------------------------------------------------------------------
__global__ __launch_bounds__(256) void scan_reduce_kernel() {
    int id = blockIdx.x * blockDim.x + threadIdx.x;
    int f = id & (F_ - 1);
    int c = (id >> 7) & (NC - 1);
    int b = id >> 12;

    const __half* actb = g_actH + (size_t)(b * T_) * O_;
    const float*  Xtb  = g_Xt + (size_t)b * T_ * F_;

    float A = 1.f, Bv = 0.f;
    int t0 = c * CHUNK;
    for (int t = t0; t < t0 + CHUNK; t++) {
        float s = __half2float(actb[(size_t)t * O_ + f]);
        float x = Xtb[(size_t)t * F_ + f];
        float a = 1.f - s;
        A  *= a;
        Bv = a * Bv + s * x;
    }
    g_Ac[id] = A;
    g_Bc[id] = Bv;
}

// ---------------------------------------------------------------------------
// Scan stage B: per-(b,f) chain over NC chunk summaries (coalesced over f)
// ---------------------------------------------------------------------------
__global__ __launch_bounds__(128) void scan_chain_kernel() {
    int b = blockIdx.x, f = threadIdx.x;
    float M = 0.f;
    #pragma unroll
    for (int c = 0; c < NC; c++) {
        int idx = (b * NC + c) * F_ + f;
        g_Ms[idx] = M;
        M = g_Ac[idx] * M + g_Bc[idx];
    }
}

// ---------------------------------------------------------------------------
// Scan stage C: replay + PCEN epilogue; smem transpose for coalesced output
// block = (b*NC + c), 128 threads = f
// ---------------------------------------------------------------------------
__global__ __launch_bounds__(128) void scan_final_kernel(float* __restrict__ out) {
    __shared__ float tile[32][129];
    int bc = blockIdx.x;
    int b = bc >> 5;           // /NC
    int c = bc & (NC - 1);
    int f = threadIdx.x;
    int lane = f & 31, wid = f >> 5;

    const __half* actb = g_actH + (size_t)(b * T_) * O_;
    const float*  Xtb  = g_Xt + (size_t)b * T_ * F_;

    float M = g_Ms[bc * F_ + f];
    int t0 = c * CHUNK, t1 = t0 + CHUNK;
    for (int tb = t0; tb < t1; tb += 32) {
        int nrow = min(32, t1 - tb);
        for (int q = 0; q < nrow; q++) {
            int t = tb + q;
            const __half* rowp = actb + (size_t)t * O_;
            float s     = __half2float(rowp[f]);
            float alpha = __half2float(rowp[128 + f]);
            float delta = __half2float(rowp[256 + f]);
            float r     = __half2float(rowp[384 + f]);
            float x = Xtb[(size_t)t * F_ + f];
            M = (1.f - s) * M + s * x;
            float base = x * __powf(M + EPS, -alpha) + delta;
            tile[q][f] = __powf(base, r) - __powf(delta, r);
        }
        __syncthreads();
        #pragma unroll
        for (int ff = wid; ff < 128; ff += 4) {
            if (lane < nrow)
                out[(size_t)(b * F_ + ff) * T_ + tb + lane] = tile[lane][ff];
        }
        __syncthreads();
    }
}

// ---------------------------------------------------------------------------
// Launch
// ---------------------------------------------------------------------------
extern "C" void kernel_launch(void* const* d_in, const int* in_sizes, int n_in,
                              void* d_out, int out_size) {
    const float* X  = (const float*)d_in[0];
    const float* W1 = (const float*)d_in[1];
    const float* b1 = (const float*)d_in[2];
    const float* W2 = (const float*)d_in[3];
    const float* b2 = (const float*)d_in[4];
    float* out = (float*)d_out;

    float *Xt;
    __half *Xf, *W1f, *W2f;
    cudaGetSymbolAddress((void**)&Xt,  g_Xt);
    cudaGetSymbolAddress((void**)&Xf,  g_Xf);
    cudaGetSymbolAddress((void**)&W1f, g_W1f);
    cudaGetSymbolAddress((void**)&W2f, g_W2f);

    // Idempotent host-side attribute set (no stream interaction; capture-safe)
    cudaFuncSetAttribute(gemm_mma<1>, cudaFuncAttributeMaxDynamicSharedMemorySize, SMEM_GEMM);
    cudaFuncSetAttribute(gemm_mma<2>, cudaFuncAttributeMaxDynamicSharedMemorySize, SMEM_GEMM);

    // X [F][T] per batch -> Xt(fp32)+Xf(fp16) [T][F]; W1 -> [H][K]; W2 -> [O][K]
    transpose_conv<<<dim3(T_ / 32, F_ / 32, B_), dim3(32, 8)>>>(X, Xt, Xf, F_, T_);
    transpose_conv<<<dim3(H_ / 32, KDIM / 32, 1), dim3(32, 8)>>>(W1, nullptr, W1f, KDIM, H_);
    transpose_conv<<<dim3(O_ / 32, KDIM / 32, 1), dim3(32, 8)>>>(W2, nullptr, W2f, KDIM, O_);

    gemm_mma<1><<<dim3(H_ / BN, (B_ * T_) / BM), 256, SMEM_GEMM>>>(b1);   // (2, 1000)
    gemm_mma<2><<<dim3(O_ / BN, (B_ * T_) / BM), 256, SMEM_GEMM>>>(b2);   // (4, 1000)

    scan_reduce_kernel<<<(B_ * F_ * NC) / 256, 256>>>();
    scan_chain_kernel<<<B_, 128>>>();
    scan_final_kernel<<<B_ * NC, 128>>>(out);
}

// round 12
// speedup vs baseline: 1.3039x; 1.0778x over previous
#include <cuda_runtime.h>
#include <cuda_fp16.h>
#include <math.h>
#include <stdint.h>

// Problem constants
#define B_   32
#define F_   128
#define T_   4000
#define H_   256     // hidden
#define O_   512     // 4F
#define KDIM 256     // 2F
#define EPS  1e-6f

// Scan chunking: 125 chunks of 32 -> 4000
#define CHUNK 32
#define NC    125
#define CHAIN_SMEM (NC * F_ * 2 * 4)   // 128000 B

// GEMM tiling
#define BM 128
#define BN 128
#define BK 64
#define ROWB 128                  // smem row stride bytes (8x16B chunks, XOR swizzle)
#define PL   (BM * ROWB)          // one plane: 16384 B
#define SSTR (2 * PL)             // one stage (A, B): 32768 B
#define NSTAGE 3
#define SMEM_GEMM (NSTAGE * SSTR) // 98304 B
#define NKC (KDIM / BK)           // 4 K-chunks

// ---------------------------------------------------------------------------
// Scratch (device globals)
// ---------------------------------------------------------------------------
__device__ __align__(128) float   g_Xt  [B_ * T_ * F_];   // fp32 [b][t][f] for scans
__device__ __align__(128) __half  g_Xf  [B_ * T_ * F_];   // fp16 [b][t][f] for GEMM1
__device__ __align__(128) __half  g_W1f [H_ * KDIM];
__device__ __align__(128) __half  g_W2f [O_ * KDIM];
__device__ __align__(128) __half  g_Hf  [B_ * T_ * H_];
__device__ __align__(128) __half  g_actH[B_ * T_ * O_];   // fp16 activations
__device__ float g_Ac[B_ * NC * F_];    // [b][c][f]
__device__ float g_Bc[B_ * NC * F_];
__device__ float g_Ms[B_ * NC * F_];

// ---------------------------------------------------------------------------
// Helpers
// ---------------------------------------------------------------------------
__device__ __forceinline__ uint32_t smem_u32(const void* p) {
    uint32_t a;
    asm("{ .reg .u64 t; cvta.to.shared.u64 t, %1; cvt.u32.u64 %0, t; }" : "=r"(a) : "l"(p));
    return a;
}
__device__ __forceinline__ void cp16(uint32_t dst, const void* src) {
    asm volatile("cp.async.cg.shared.global [%0], [%1], 16;" :: "r"(dst), "l"(src) : "memory");
}
#define CP_COMMIT() asm volatile("cp.async.commit_group;" ::: "memory")
#define CP_WAIT1()  asm volatile("cp.async.wait_group 1;" ::: "memory")

__device__ __forceinline__ void ldsm_x4(uint32_t& r0, uint32_t& r1, uint32_t& r2, uint32_t& r3,
                                        uint32_t addr) {
    asm volatile("ldmatrix.sync.aligned.m8n8.x4.shared.b16 {%0,%1,%2,%3}, [%4];"
                 : "=r"(r0), "=r"(r1), "=r"(r2), "=r"(r3) : "r"(addr));
}
__device__ __forceinline__ void mma_fp16(float* c, const uint32_t* a, const uint32_t* b) {
    asm volatile("mma.sync.aligned.m16n8k16.row.col.f32.f16.f16.f32 "
                 "{%0,%1,%2,%3}, {%4,%5,%6,%7}, {%8,%9}, {%0,%1,%2,%3};"
                 : "+f"(c[0]), "+f"(c[1]), "+f"(c[2]), "+f"(c[3])
                 : "r"(a[0]), "r"(a[1]), "r"(a[2]), "r"(a[3]), "r"(b[0]), "r"(b[1]));
}
__device__ __forceinline__ uint32_t pack_h2(float x, float y) {
    __half2 h = __floats2half2_rn(x, y);
    return *(uint32_t*)&h;
}

// ---------------------------------------------------------------------------
// Transpose + fp16 convert: in [R][C] fp32 -> out [C][R] (fp32 optional, fp16)
// ---------------------------------------------------------------------------
__global__ void transpose_conv(const float* __restrict__ in, float* __restrict__ outF,
                               __half* __restrict__ outH, int R, int C) {
    __shared__ float tile[32][33];
    size_t boff = (size_t)blockIdx.z * R * C;
    in += boff;
    int c0 = blockIdx.x * 32, r0 = blockIdx.y * 32;
    int x = threadIdx.x, y = threadIdx.y;
    #pragma unroll
    for (int i = 0; i < 32; i += 8)
        tile[y + i][x] = in[(size_t)(r0 + y + i) * C + c0 + x];
    __syncthreads();
    #pragma unroll
    for (int i = 0; i < 32; i += 8) {
        float v = tile[x][y + i];
        size_t idx = boff + (size_t)(c0 + y + i) * R + r0 + x;
        if (outF) outF[idx] = v;
        outH[idx] = __float2half_rn(v);
    }
}

// ---------------------------------------------------------------------------
// GEMM via fp16 mma.sync, BK=64, 3-stage cp.async pipeline, XOR-swizzled smem.
// MODE 1: Hf   = relu(concat(X[:,t-1],X[:,t]) @ W1 + b1)   [128000 x 256]
// MODE 2: actH = activation(h @ W2 + b2)                   [128000 x 512]
// ---------------------------------------------------------------------------
template<int MODE>
__global__ __launch_bounds__(256, 2) void gemm_mma(const float* __restrict__ bias) {
    extern __shared__ __align__(128) char sm[];
    const int tid = threadIdx.x;
    const int lane = tid & 31;
    const int wid = tid >> 5;
    const int wm = wid >> 2;
    const int wn = wid & 3;
    const int n0 = blockIdx.x * BN;
    const int m0 = blockIdx.y * BM;

    const uint32_t smbase = smem_u32(sm);

    // staging: thread item p -> row = (tid>>3) + 32p, chunk k = tid&7
    const int st_row = tid >> 3;            // 0..31
    const int st_k   = tid & 7;             // 16B chunk in row
    const uint32_t st_sw = (uint32_t)(st_row & 7);
    const uint32_t st_d0 = (uint32_t)st_row * ROWB + (((uint32_t)st_k ^ st_sw) << 4);

    const __half* AF = (MODE == 1) ? g_Xf : g_Hf;
    const __half* WF = (MODE == 1) ? g_W1f : g_W2f;

    size_t acur[4], aprev[4], boff[4];
    #pragma unroll
    for (int p = 0; p < 4; p++) {
        int row = st_row + 32 * p;
        if (MODE == 1) {
            int gr = m0 + row;
            int b = gr / T_;
            int t = gr - b * T_;
            int tp = t ? (t - 1) : 0;
            acur[p]  = ((size_t)b * T_ + t)  * F_ + st_k * 8;
            aprev[p] = ((size_t)b * T_ + tp) * F_ + st_k * 8;
        } else {
            acur[p] = (size_t)(m0 + row) * H_ + st_k * 8;
        }
        boff[p] = (size_t)(n0 + row) * KDIM + st_k * 8;
    }

    auto stage = [&](int c, int slot) {
        const int k0 = c * BK;
        uint32_t sA = smbase + slot * SSTR;
        #pragma unroll
        for (int p = 0; p < 4; p++) {
            uint32_t d = st_d0 + p * (32 * ROWB);
            size_t so;
            if (MODE == 1) so = (k0 < 128) ? (aprev[p] + k0) : (acur[p] + (k0 - 128));
            else           so = acur[p] + k0;
            cp16(sA + d,      AF + so);
            cp16(sA + PL + d, WF + boff[p] + k0);
        }
    };

    float acc[4][4][4];
    #pragma unroll
    for (int i = 0; i < 4; i++)
        #pragma unroll
        for (int j = 0; j < 4; j++)
            #pragma unroll
            for (int q = 0; q < 4; q++) acc[i][j][q] = 0.f;

    // ldmatrix addressing: all row offsets are multiples of 8 -> (row&7) const
    const uint32_t a_rowb = (uint32_t)(wm * 64) + (lane & 15);
    const uint32_t a_half = (uint32_t)lane >> 4;                 // 0/1
    const uint32_t b_rowb = (uint32_t)(wn * 32) + (((uint32_t)lane >> 4) << 3) + (lane & 7);
    const uint32_t b_half = ((uint32_t)lane >> 3) & 1;
    const uint32_t sw_a   = a_rowb & 7;
    const uint32_t sw_b   = b_rowb & 7;

    stage(0, 0); CP_COMMIT();
    stage(1, 1); CP_COMMIT();

    #pragma unroll 1
    for (int c = 0; c < NKC; c++) {
        CP_WAIT1();                  // group c complete (c+1 may be in flight)
        __syncthreads();             // all warps done reading slot (c-1)%3
        if (c + 2 < NKC) stage(c + 2, (c + 2) % NSTAGE);
        CP_COMMIT();

        const int slot = c % NSTAGE;
        const uint32_t sA = smbase + slot * SSTR;
        const uint32_t sB = sA + PL;

        #pragma unroll
        for (int s = 0; s < 4; s++) {
            const uint32_t a_co = ((2 * s + a_half) ^ sw_a) << 4;
            const uint32_t b_co = ((2 * s + b_half) ^ sw_b) << 4;
            uint32_t bf[4][2];
            #pragma unroll
            for (int jj = 0; jj < 2; jj++) {
                uint32_t off = (b_rowb + jj * 16) * ROWB + b_co;
                uint32_t r0, r1, r2, r3;
                ldsm_x4(r0, r1, r2, r3, sB + off);
                bf[2 * jj][0] = r0; bf[2 * jj][1] = r1;
                bf[2 * jj + 1][0] = r2; bf[2 * jj + 1][1] = r3;
            }
            #pragma unroll
            for (int i = 0; i < 4; i++) {
                uint32_t off = (a_rowb + i * 16) * ROWB + a_co;
                uint32_t af[4];
                ldsm_x4(af[0], af[1], af[2], af[3], sA + off);
                #pragma unroll
                for (int j = 0; j < 4; j++)
                    mma_fp16(acc[i][j], af, bf[j]);
            }
        }
    }

    // ---- epilogue ----
    const int rloc = lane >> 2;
    const int cpair = (lane & 3) * 2;
    #pragma unroll
    for (int i = 0; i < 4; i++) {
        int r0 = m0 + wm * 64 + i * 16 + rloc;
        int r1 = r0 + 8;
        #pragma unroll
        for (int j = 0; j < 4; j++) {
            int ng = n0 + wn * 32 + j * 8 + cpair;
            float2 bb = *(const float2*)&bias[ng];
            float u0 = acc[i][j][0] + bb.x, u1 = acc[i][j][1] + bb.y;
            float u2 = acc[i][j][2] + bb.x, u3 = acc[i][j][3] + bb.y;
            if (MODE == 1) {
                u0 = fmaxf(u0, 0.f); u1 = fmaxf(u1, 0.f);
                u2 = fmaxf(u2, 0.f); u3 = fmaxf(u3, 0.f);
                *(uint32_t*)&g_Hf[(size_t)r0 * H_ + ng] = pack_h2(u0, u1);
                *(uint32_t*)&g_Hf[(size_t)r1 * H_ + ng] = pack_h2(u2, u3);
            } else {
                bool sp = (blockIdx.x == 2);   // cols [256,384): softplus (delta)
                float uu[4] = {u0, u1, u2, u3};
                float v[4];
                #pragma unroll
                for (int q = 0; q < 4; q++) {
                    float u = uu[q];
                    v[q] = sp ? (__logf(1.f + __expf(-fabsf(u))) + fmaxf(u, 0.f))
                              : (1.f / (1.f + __expf(-u)));
                }
                *(uint32_t*)&g_actH[(size_t)r0 * O_ + ng] = pack_h2(v[0], v[1]);
                *(uint32_t*)&g_actH[(size_t)r1 * O_ + ng] = pack_h2(v[2], v[3]);
            }
        }
    }
}

// ---------------------------------------------------------------------------
// Scan stage A: per-chunk composition  (writes [b][c][f], fully coalesced)
// 512K threads / 2000 CTAs; 32-step serial chain per thread
// ---------------------------------------------------------------------------
__global__ __launch_bounds__(256) void scan_reduce_kernel() {
    int id = blockIdx.x * blockDim.x + threadIdx.x;
    int f = id & (F_ - 1);
    int r = id >> 7;
    int c = r % NC;
    int b = r / NC;

    const __half* actb = g_actH + (size_t)(b * T_) * O_;
    const float*  Xtb  = g_Xt + (size_t)b * T_ * F_;

    float A = 1.f, Bv = 0.f;
    int t0 = c * CHUNK;
    #pragma unroll 4
    for (int t = t0; t < t0 + CHUNK; t++) {
        float s = __half2float(actb[(size_t)t * O_ + f]);
        float x = Xtb[(size_t)t * F_ + f];
        float a = 1.f - s;
        A  *= a;
        Bv = a * Bv + s * x;
    }
    g_Ac[id] = A;
    g_Bc[id] = Bv;
}

// ---------------------------------------------------------------------------
// Scan stage B: per-(b,f) chain over NC chunk summaries, smem-cached.
// One CTA per batch: coalesced bulk load of all (A,B), then in-smem scan.
// ---------------------------------------------------------------------------
__global__ __launch_bounds__(128) void scan_chain_kernel() {
    extern __shared__ float chsm[];              // As[NC*F_], Bs[NC*F_]
    float* As = chsm;
    float* Bs = chsm + NC * F_;
    int b = blockIdx.x, f = threadIdx.x;
    int base = b * NC * F_;

    for (int i = f; i < NC * F_; i += 128) {
        As[i] = g_Ac[base + i];
        Bs[i] = g_Bc[base + i];
    }
    __syncthreads();

    float M = 0.f;
    #pragma unroll 5
    for (int c = 0; c < NC; c++) {
        g_Ms[base + c * F_ + f] = M;
        M = As[c * F_ + f] * M + Bs[c * F_ + f];
    }
}

// ---------------------------------------------------------------------------
// Scan stage C: replay + PCEN epilogue; one 32x128 transpose tile per CTA.
// grid = B_*NC = 4000 blocks, 128 threads = f
// ---------------------------------------------------------------------------
__global__ __launch_bounds__(128) void scan_final_kernel(float* __restrict__ out) {
    __shared__ float tile[32][129];
    int bc = blockIdx.x;
    int b = bc / NC;
    int c = bc % NC;
    int f = threadIdx.x;
    int lane = f & 31, wid = f >> 5;

    const __half* actb = g_actH + (size_t)(b * T_) * O_;
    const float*  Xtb  = g_Xt + (size_t)b * T_ * F_;

    float M = g_Ms[(b * NC + c) * F_ + f];
    int t0 = c * CHUNK;
    #pragma unroll 4
    for (int q = 0; q < CHUNK; q++) {
        int t = t0 + q;
        const __half* rowp = actb + (size_t)t * O_;
        float s     = __half2float(rowp[f]);
        float alpha = __half2float(rowp[128 + f]);
        float delta = __half2float(rowp[256 + f]);
        float r     = __half2float(rowp[384 + f]);
        float x = Xtb[(size_t)t * F_ + f];
        M = (1.f - s) * M + s * x;
        float base = x * __powf(M + EPS, -alpha) + delta;
        tile[q][f] = __powf(base, r) - __powf(delta, r);
    }
    __syncthreads();
    #pragma unroll
    for (int ff = wid; ff < 128; ff += 4)
        out[(size_t)(b * F_ + ff) * T_ + t0 + lane] = tile[lane][ff];
}

// ---------------------------------------------------------------------------
// Launch
// ---------------------------------------------------------------------------
extern "C" void kernel_launch(void* const* d_in, const int* in_sizes, int n_in,
                              void* d_out, int out_size) {
    const float* X  = (const float*)d_in[0];
    const float* W1 = (const float*)d_in[1];
    const float* b1 = (const float*)d_in[2];
    const float* W2 = (const float*)d_in[3];
    const float* b2 = (const float*)d_in[4];
    float* out = (float*)d_out;

    float *Xt;
    __half *Xf, *W1f, *W2f;
    cudaGetSymbolAddress((void**)&Xt,  g_Xt);
    cudaGetSymbolAddress((void**)&Xf,  g_Xf);
    cudaGetSymbolAddress((void**)&W1f, g_W1f);
    cudaGetSymbolAddress((void**)&W2f, g_W2f);

    // Idempotent host-side attribute sets (no stream interaction; capture-safe)
    cudaFuncSetAttribute(gemm_mma<1>, cudaFuncAttributeMaxDynamicSharedMemorySize, SMEM_GEMM);
    cudaFuncSetAttribute(gemm_mma<2>, cudaFuncAttributeMaxDynamicSharedMemorySize, SMEM_GEMM);
    cudaFuncSetAttribute(scan_chain_kernel, cudaFuncAttributeMaxDynamicSharedMemorySize, CHAIN_SMEM);

    // X [F][T] per batch -> Xt(fp32)+Xf(fp16) [T][F]; W1 -> [H][K]; W2 -> [O][K]
    transpose_conv<<<dim3(T_ / 32, F_ / 32, B_), dim3(32, 8)>>>(X, Xt, Xf, F_, T_);
    transpose_conv<<<dim3(H_ / 32, KDIM / 32, 1), dim3(32, 8)>>>(W1, nullptr, W1f, KDIM, H_);
    transpose_conv<<<dim3(O_ / 32, KDIM / 32, 1), dim3(32, 8)>>>(W2, nullptr, W2f, KDIM, O_);

    gemm_mma<1><<<dim3(H_ / BN, (B_ * T_) / BM), 256, SMEM_GEMM>>>(b1);   // (2, 1000)
    gemm_mma<2><<<dim3(O_ / BN, (B_ * T_) / BM), 256, SMEM_GEMM>>>(b2);   // (4, 1000)

    scan_reduce_kernel<<<(B_ * NC * F_) / 256, 256>>>();
    scan_chain_kernel<<<B_, 128, CHAIN_SMEM>>>();
    scan_final_kernel<<<B_ * NC, 128>>>(out);
}

// round 13
// speedup vs baseline: 1.3487x; 1.0344x over previous
#include <cuda_runtime.h>
#include <cuda_fp16.h>
#include <math.h>
#include <stdint.h>

// Problem constants
#define B_   32
#define F_   128
#define T_   4000
#define H_   256     // hidden
#define O_   512     // 4F
#define KDIM 256     // 2F
#define EPS  1e-6f

// Scan chunking: 125 chunks of 32 -> 4000
#define CHUNK 32
#define NC    125
#define CHAIN_SMEM (NC * F_ * 2 * 4)   // 128000 B

// GEMM tiling
#define BM 128
#define BN 128
#define BK 64
#define ROWB 128                  // smem row stride bytes (8x16B chunks, XOR swizzle)
#define PL   (BM * ROWB)          // one plane: 16384 B
#define SSTR (2 * PL)             // one stage (A, B): 32768 B
#define NSTAGE 3
#define SMEM_GEMM (NSTAGE * SSTR) // 98304 B
#define NKC (KDIM / BK)           // 4 K-chunks

// ---------------------------------------------------------------------------
// Scratch (device globals)
// ---------------------------------------------------------------------------
__device__ __align__(128) __half  g_Xf  [B_ * T_ * F_];   // fp16 [b][t][f] (GEMM1 + scans)
__device__ __align__(128) __half  g_W1f [H_ * KDIM];
__device__ __align__(128) __half  g_W2f [O_ * KDIM];
__device__ __align__(128) __half  g_Hf  [B_ * T_ * H_];
__device__ __align__(128) __half  g_actH[B_ * T_ * O_];   // fp16 activations
__device__ float g_Ac[B_ * NC * F_];    // [b][c][f]
__device__ float g_Bc[B_ * NC * F_];
__device__ float g_Ms[B_ * NC * F_];

// ---------------------------------------------------------------------------
// Helpers
// ---------------------------------------------------------------------------
__device__ __forceinline__ uint32_t smem_u32(const void* p) {
    uint32_t a;
    asm("{ .reg .u64 t; cvta.to.shared.u64 t, %1; cvt.u32.u64 %0, t; }" : "=r"(a) : "l"(p));
    return a;
}
__device__ __forceinline__ void cp16(uint32_t dst, const void* src) {
    asm volatile("cp.async.cg.shared.global [%0], [%1], 16;" :: "r"(dst), "l"(src) : "memory");
}
#define CP_COMMIT() asm volatile("cp.async.commit_group;" ::: "memory")
#define CP_WAIT1()  asm volatile("cp.async.wait_group 1;" ::: "memory")

__device__ __forceinline__ void ldsm_x4(uint32_t& r0, uint32_t& r1, uint32_t& r2, uint32_t& r3,
                                        uint32_t addr) {
    asm volatile("ldmatrix.sync.aligned.m8n8.x4.shared.b16 {%0,%1,%2,%3}, [%4];"
                 : "=r"(r0), "=r"(r1), "=r"(r2), "=r"(r3) : "r"(addr));
}
__device__ __forceinline__ void mma_fp16(float* c, const uint32_t* a, const uint32_t* b) {
    asm volatile("mma.sync.aligned.m16n8k16.row.col.f32.f16.f16.f32 "
                 "{%0,%1,%2,%3}, {%4,%5,%6,%7}, {%8,%9}, {%0,%1,%2,%3};"
                 : "+f"(c[0]), "+f"(c[1]), "+f"(c[2]), "+f"(c[3])
                 : "r"(a[0]), "r"(a[1]), "r"(a[2]), "r"(a[3]), "r"(b[0]), "r"(b[1]));
}
__device__ __forceinline__ uint32_t pack_h2(float x, float y) {
    __half2 h = __floats2half2_rn(x, y);
    return *(uint32_t*)&h;
}

// ---------------------------------------------------------------------------
// Transpose + fp16 convert: in [R][C] fp32 -> out [C][R] fp16
// ---------------------------------------------------------------------------
__global__ void transpose_conv(const float* __restrict__ in, __half* __restrict__ outH,
                               int R, int C) {
    __shared__ float tile[32][33];
    size_t boff = (size_t)blockIdx.z * R * C;
    in += boff;
    int c0 = blockIdx.x * 32, r0 = blockIdx.y * 32;
    int x = threadIdx.x, y = threadIdx.y;
    #pragma unroll
    for (int i = 0; i < 32; i += 8)
        tile[y + i][x] = in[(size_t)(r0 + y + i) * C + c0 + x];
    __syncthreads();
    #pragma unroll
    for (int i = 0; i < 32; i += 8) {
        float v = tile[x][y + i];
        outH[boff + (size_t)(c0 + y + i) * R + r0 + x] = __float2half_rn(v);
    }
}

// ---------------------------------------------------------------------------
// GEMM via fp16 mma.sync, BK=64, 3-stage cp.async pipeline, XOR-swizzled smem,
// B-fragments hoisted per chunk (8 independent LDSM after each barrier).
// MODE 1: Hf   = relu(concat(X[:,t-1],X[:,t]) @ W1 + b1)   [128000 x 256]
// MODE 2: actH = activation(h @ W2 + b2)                   [128000 x 512]
// ---------------------------------------------------------------------------
template<int MODE>
__global__ __launch_bounds__(256, 2) void gemm_mma(const float* __restrict__ bias) {
    extern __shared__ __align__(128) char sm[];
    const int tid = threadIdx.x;
    const int lane = tid & 31;
    const int wid = tid >> 5;
    const int wm = wid >> 2;
    const int wn = wid & 3;
    const int n0 = blockIdx.x * BN;
    const int m0 = blockIdx.y * BM;

    const uint32_t smbase = smem_u32(sm);

    // staging: thread item p -> row = (tid>>3) + 32p, chunk k = tid&7
    const int st_row = tid >> 3;            // 0..31
    const int st_k   = tid & 7;             // 16B chunk in row
    const uint32_t st_sw = (uint32_t)(st_row & 7);
    const uint32_t st_d0 = (uint32_t)st_row * ROWB + (((uint32_t)st_k ^ st_sw) << 4);

    const __half* AF = (MODE == 1) ? g_Xf : g_Hf;
    const __half* WF = (MODE == 1) ? g_W1f : g_W2f;

    size_t acur[4], aprev[4], boff[4];
    #pragma unroll
    for (int p = 0; p < 4; p++) {
        int row = st_row + 32 * p;
        if (MODE == 1) {
            int gr = m0 + row;
            int b = gr / T_;
            int t = gr - b * T_;
            int tp = t ? (t - 1) : 0;
            acur[p]  = ((size_t)b * T_ + t)  * F_ + st_k * 8;
            aprev[p] = ((size_t)b * T_ + tp) * F_ + st_k * 8;
        } else {
            acur[p] = (size_t)(m0 + row) * H_ + st_k * 8;
        }
        boff[p] = (size_t)(n0 + row) * KDIM + st_k * 8;
    }

    auto stage = [&](int c, int slot) {
        const int k0 = c * BK;
        uint32_t sA = smbase + slot * SSTR;
        #pragma unroll
        for (int p = 0; p < 4; p++) {
            uint32_t d = st_d0 + p * (32 * ROWB);
            size_t so;
            if (MODE == 1) so = (k0 < 128) ? (aprev[p] + k0) : (acur[p] + (k0 - 128));
            else           so = acur[p] + k0;
            cp16(sA + d,      AF + so);
            cp16(sA + PL + d, WF + boff[p] + k0);
        }
    };

    float acc[4][4][4];
    #pragma unroll
    for (int i = 0; i < 4; i++)
        #pragma unroll
        for (int j = 0; j < 4; j++)
            #pragma unroll
            for (int q = 0; q < 4; q++) acc[i][j][q] = 0.f;

    // ldmatrix addressing: all row offsets are multiples of 8 -> (row&7) const
    const uint32_t a_rowb = (uint32_t)(wm * 64) + (lane & 15);
    const uint32_t a_half = (uint32_t)lane >> 4;                 // 0/1
    const uint32_t b_rowb = (uint32_t)(wn * 32) + (((uint32_t)lane >> 4) << 3) + (lane & 7);
    const uint32_t b_half = ((uint32_t)lane >> 3) & 1;
    const uint32_t sw_a   = a_rowb & 7;
    const uint32_t sw_b   = b_rowb & 7;

    stage(0, 0); CP_COMMIT();
    stage(1, 1); CP_COMMIT();

    #pragma unroll 1
    for (int c = 0; c < NKC; c++) {
        CP_WAIT1();                  // group c complete (c+1 may be in flight)
        __syncthreads();             // all warps done reading slot (c-1)%3
        if (c + 2 < NKC) stage(c + 2, (c + 2) % NSTAGE);
        CP_COMMIT();

        const int slot = c % NSTAGE;
        const uint32_t sA = smbase + slot * SSTR;
        const uint32_t sB = sA + PL;

        // Hoist all B fragments for this chunk: 8 independent LDSM
        uint32_t bfall[4][4][2];
        #pragma unroll
        for (int s = 0; s < 4; s++) {
            const uint32_t b_co = ((2 * s + b_half) ^ sw_b) << 4;
            #pragma unroll
            for (int jj = 0; jj < 2; jj++) {
                uint32_t off = (b_rowb + jj * 16) * ROWB + b_co;
                uint32_t r0, r1, r2, r3;
                ldsm_x4(r0, r1, r2, r3, sB + off);
                bfall[s][2 * jj][0] = r0;     bfall[s][2 * jj][1] = r1;
                bfall[s][2 * jj + 1][0] = r2; bfall[s][2 * jj + 1][1] = r3;
            }
        }

        #pragma unroll
        for (int s = 0; s < 4; s++) {
            const uint32_t a_co = ((2 * s + a_half) ^ sw_a) << 4;
            #pragma unroll
            for (int i = 0; i < 4; i++) {
                uint32_t off = (a_rowb + i * 16) * ROWB + a_co;
                uint32_t af[4];
                ldsm_x4(af[0], af[1], af[2], af[3], sA + off);
                #pragma unroll
                for (int j = 0; j < 4; j++)
                    mma_fp16(acc[i][j], af, bfall[s][j]);
            }
        }
    }

    // ---- epilogue ----
    const int rloc = lane >> 2;
    const int cpair = (lane & 3) * 2;
    #pragma unroll
    for (int i = 0; i < 4; i++) {
        int r0 = m0 + wm * 64 + i * 16 + rloc;
        int r1 = r0 + 8;
        #pragma unroll
        for (int j = 0; j < 4; j++) {
            int ng = n0 + wn * 32 + j * 8 + cpair;
            float2 bb = *(const float2*)&bias[ng];
            float u0 = acc[i][j][0] + bb.x, u1 = acc[i][j][1] + bb.y;
            float u2 = acc[i][j][2] + bb.x, u3 = acc[i][j][3] + bb.y;
            if (MODE == 1) {
                u0 = fmaxf(u0, 0.f); u1 = fmaxf(u1, 0.f);
                u2 = fmaxf(u2, 0.f); u3 = fmaxf(u3, 0.f);
                *(uint32_t*)&g_Hf[(size_t)r0 * H_ + ng] = pack_h2(u0, u1);
                *(uint32_t*)&g_Hf[(size_t)r1 * H_ + ng] = pack_h2(u2, u3);
            } else {
                bool sp = (blockIdx.x == 2);   // cols [256,384): softplus (delta)
                float uu[4] = {u0, u1, u2, u3};
                float v[4];
                #pragma unroll
                for (int q = 0; q < 4; q++) {
                    float u = uu[q];
                    v[q] = sp ? (__logf(1.f + __expf(-fabsf(u))) + fmaxf(u, 0.f))
                              : (1.f / (1.f + __expf(-u)));
                }
                *(uint32_t*)&g_actH[(size_t)r0 * O_ + ng] = pack_h2(v[0], v[1]);
                *(uint32_t*)&g_actH[(size_t)r1 * O_ + ng] = pack_h2(v[2], v[3]);
            }
        }
    }
}

// ---------------------------------------------------------------------------
// Scan stage A: per-chunk composition  (writes [b][c][f], fully coalesced)
// 512K threads / 2000 CTAs; 32-step serial chain per thread
// ---------------------------------------------------------------------------
__global__ __launch_bounds__(256) void scan_reduce_kernel() {
    int id = blockIdx.x * blockDim.x + threadIdx.x;
    int f = id & (F_ - 1);
    int r = id >> 7;
    int c = r % NC;
    int b = r / NC;

    const __half* actb = g_actH + (size_t)(b * T_) * O_;
    const __half* Xfb  = g_Xf + (size_t)b * T_ * F_;

    float A = 1.f, Bv = 0.f;
    int t0 = c * CHUNK;
    #pragma unroll 4
    for (int t = t0; t < t0 + CHUNK; t++) {
        float s = __half2float(actb[(size_t)t * O_ + f]);
        float x = __half2float(Xfb[(size_t)t * F_ + f]);
        float a = 1.f - s;
        A  *= a;
        Bv = a * Bv + s * x;
    }
    g_Ac[id] = A;
    g_Bc[id] = Bv;
}

// ---------------------------------------------------------------------------
// Scan stage B: per-(b,f) chain over NC chunk summaries, smem-cached.
// One CTA per batch: coalesced bulk load of all (A,B), then in-smem scan.
// ---------------------------------------------------------------------------
__global__ __launch_bounds__(128) void scan_chain_kernel() {
    extern __shared__ float chsm[];              // As[NC*F_], Bs[NC*F_]
    float* As = chsm;
    float* Bs = chsm + NC * F_;
    int b = blockIdx.x, f = threadIdx.x;
    int base = b * NC * F_;

    for (int i = f; i < NC * F_; i += 128) {
        As[i] = g_Ac[base + i];
        Bs[i] = g_Bc[base + i];
    }
    __syncthreads();

    float M = 0.f;
    #pragma unroll 5
    for (int c = 0; c < NC; c++) {
        g_Ms[base + c * F_ + f] = M;
        M = As[c * F_ + f] * M + Bs[c * F_ + f];
    }
}

// ---------------------------------------------------------------------------
// Scan stage C: replay + PCEN epilogue; one 32x128 transpose tile per CTA.
// grid = B_*NC = 4000 blocks, 128 threads = f
// ---------------------------------------------------------------------------
__global__ __launch_bounds__(128) void scan_final_kernel(float* __restrict__ out) {
    __shared__ float tile[32][129];
    int bc = blockIdx.x;
    int b = bc / NC;
    int c = bc % NC;
    int f = threadIdx.x;
    int lane = f & 31, wid = f >> 5;

    const __half* actb = g_actH + (size_t)(b * T_) * O_;
    const __half* Xfb  = g_Xf + (size_t)b * T_ * F_;

    float M = g_Ms[(b * NC + c) * F_ + f];
    int t0 = c * CHUNK;
    #pragma unroll 4
    for (int q = 0; q < CHUNK; q++) {
        int t = t0 + q;
        const __half* rowp = actb + (size_t)t * O_;
        float s     = __half2float(rowp[f]);
        float alpha = __half2float(rowp[128 + f]);
        float delta = __half2float(rowp[256 + f]);
        float r     = __half2float(rowp[384 + f]);
        float x = __half2float(Xfb[(size_t)t * F_ + f]);
        M = (1.f - s) * M + s * x;
        float base = x * __powf(M + EPS, -alpha) + delta;
        tile[q][f] = __powf(base, r) - __powf(delta, r);
    }
    __syncthreads();
    #pragma unroll
    for (int ff = wid; ff < 128; ff += 4)
        out[(size_t)(b * F_ + ff) * T_ + t0 + lane] = tile[lane][ff];
}

// ---------------------------------------------------------------------------
// Launch
// ---------------------------------------------------------------------------
extern "C" void kernel_launch(void* const* d_in, const int* in_sizes, int n_in,
                              void* d_out, int out_size) {
    const float* X  = (const float*)d_in[0];
    const float* W1 = (const float*)d_in[1];
    const float* b1 = (const float*)d_in[2];
    const float* W2 = (const float*)d_in[3];
    const float* b2 = (const float*)d_in[4];
    float* out = (float*)d_out;

    __half *Xf, *W1f, *W2f;
    cudaGetSymbolAddress((void**)&Xf,  g_Xf);
    cudaGetSymbolAddress((void**)&W1f, g_W1f);
    cudaGetSymbolAddress((void**)&W2f, g_W2f);

    // Idempotent host-side attribute sets (no stream interaction; capture-safe)
    cudaFuncSetAttribute(gemm_mma<1>, cudaFuncAttributeMaxDynamicSharedMemorySize, SMEM_GEMM);
    cudaFuncSetAttribute(gemm_mma<2>, cudaFuncAttributeMaxDynamicSharedMemorySize, SMEM_GEMM);
    cudaFuncSetAttribute(scan_chain_kernel, cudaFuncAttributeMaxDynamicSharedMemorySize, CHAIN_SMEM);

    // X [F][T] per batch -> Xf(fp16) [T][F]; W1 -> [H][K]; W2 -> [O][K]
    transpose_conv<<<dim3(T_ / 32, F_ / 32, B_), dim3(32, 8)>>>(X, Xf, F_, T_);
    transpose_conv<<<dim3(H_ / 32, KDIM / 32, 1), dim3(32, 8)>>>(W1, W1f, KDIM, H_);
    transpose_conv<<<dim3(O_ / 32, KDIM / 32, 1), dim3(32, 8)>>>(W2, W2f, KDIM, O_);

    gemm_mma<1><<<dim3(H_ / BN, (B_ * T_) / BM), 256, SMEM_GEMM>>>(b1);   // (2, 1000)
    gemm_mma<2><<<dim3(O_ / BN, (B_ * T_) / BM), 256, SMEM_GEMM>>>(b2);   // (4, 1000)

    scan_reduce_kernel<<<(B_ * NC * F_) / 256, 256>>>();
    scan_chain_kernel<<<B_, 128, CHAIN_SMEM>>>();
    scan_final_kernel<<<B_ * NC, 128>>>(out);
}

// round 14
// speedup vs baseline: 1.5023x; 1.1139x over previous
#include <cuda_runtime.h>
#include <cuda_fp16.h>
#include <math.h>
#include <stdint.h>

// Problem constants
#define B_   32
#define F_   128
#define T_   4000
#define H_   256     // hidden
#define O_   512     // 4F
#define KDIM 256     // 2F
#define EPS  1e-6f

// Scan chunking: 125 chunks of 32 -> 4000
#define CHUNK 32
#define NC    125
#define CHAIN_SMEM (NC * F_ * 2 * 4)   // 128000 B

// GEMM tiling
#define BM 128
#define BN 128
#define BK 64
#define ROWB 128                  // smem row stride bytes (8x16B chunks, XOR swizzle)
#define PL   (BM * ROWB)          // one plane: 16384 B
#define SSTR (2 * PL)             // one stage (A, B): 32768 B
#define NSTAGE 3
#define SMEM_GEMM (NSTAGE * SSTR) // 98304 B
#define NKC (KDIM / BK)           // 4 K-chunks

// ---------------------------------------------------------------------------
// Scratch (device globals)
// ---------------------------------------------------------------------------
__device__ __align__(128) __half  g_Xf  [B_ * T_ * F_];   // fp16 [b][t][f] (GEMM1 + scans)
__device__ __align__(128) __half  g_W1f [H_ * KDIM];
__device__ __align__(128) __half  g_W2f [O_ * KDIM];
__device__ __align__(128) __half  g_Hf  [B_ * T_ * H_];
__device__ __align__(128) __half  g_actH[B_ * T_ * O_];   // fp16 activations
__device__ float g_Ac[B_ * NC * F_];    // [b][c][f]
__device__ float g_Bc[B_ * NC * F_];
__device__ float g_Ms[B_ * NC * F_];

// ---------------------------------------------------------------------------
// Helpers
// ---------------------------------------------------------------------------
__device__ __forceinline__ uint32_t smem_u32(const void* p) {
    uint32_t a;
    asm("{ .reg .u64 t; cvta.to.shared.u64 t, %1; cvt.u32.u64 %0, t; }" : "=r"(a) : "l"(p));
    return a;
}
__device__ __forceinline__ void cp16(uint32_t dst, const void* src) {
    asm volatile("cp.async.cg.shared.global [%0], [%1], 16;" :: "r"(dst), "l"(src) : "memory");
}
#define CP_COMMIT() asm volatile("cp.async.commit_group;" ::: "memory")
#define CP_WAIT1()  asm volatile("cp.async.wait_group 1;" ::: "memory")

__device__ __forceinline__ void ldsm_x4(uint32_t& r0, uint32_t& r1, uint32_t& r2, uint32_t& r3,
                                        uint32_t addr) {
    asm volatile("ldmatrix.sync.aligned.m8n8.x4.shared.b16 {%0,%1,%2,%3}, [%4];"
                 : "=r"(r0), "=r"(r1), "=r"(r2), "=r"(r3) : "r"(addr));
}
__device__ __forceinline__ void mma_fp16(float* c, const uint32_t* a, const uint32_t* b) {
    asm volatile("mma.sync.aligned.m16n8k16.row.col.f32.f16.f16.f32 "
                 "{%0,%1,%2,%3}, {%4,%5,%6,%7}, {%8,%9}, {%0,%1,%2,%3};"
                 : "+f"(c[0]), "+f"(c[1]), "+f"(c[2]), "+f"(c[3])
                 : "r"(a[0]), "r"(a[1]), "r"(a[2]), "r"(a[3]), "r"(b[0]), "r"(b[1]));
}
__device__ __forceinline__ uint32_t pack_h2(float x, float y) {
    __half2 h = __floats2half2_rn(x, y);
    return *(uint32_t*)&h;
}
// sigmoid via MUFU.TANH: 1 MUFU + 2 FMA (vs EX2 + RCP = 2 MUFU)
__device__ __forceinline__ float sigmoid_tanh(float x) {
    float t;
    asm("tanh.approx.f32 %0, %1;" : "=f"(t) : "f"(x * 0.5f));
    return fmaf(t, 0.5f, 0.5f);
}

// ---------------------------------------------------------------------------
// Transpose + fp16 convert: in [R][C] fp32 -> out [C][R] fp16  (X path)
// ---------------------------------------------------------------------------
__global__ void transpose_conv(const float* __restrict__ in, __half* __restrict__ outH,
                               int R, int C) {
    __shared__ float tile[32][33];
    size_t boff = (size_t)blockIdx.z * R * C;
    in += boff;
    int c0 = blockIdx.x * 32, r0 = blockIdx.y * 32;
    int x = threadIdx.x, y = threadIdx.y;
    #pragma unroll
    for (int i = 0; i < 32; i += 8)
        tile[y + i][x] = in[(size_t)(r0 + y + i) * C + c0 + x];
    __syncthreads();
    #pragma unroll
    for (int i = 0; i < 32; i += 8) {
        float v = tile[x][y + i];
        outH[boff + (size_t)(c0 + y + i) * R + r0 + x] = __float2half_rn(v);
    }
}

// ---------------------------------------------------------------------------
// Merged W1+W2 transpose: z=0 -> W1 [K][H]->[H][K], z=1 -> W2 [K][O]->[O][K]
// grid (O_/32, KDIM/32, 2); z=0 guards x < H_/32
// ---------------------------------------------------------------------------
__global__ void transpose_w(const float* __restrict__ W1, __half* __restrict__ W1f,
                            const float* __restrict__ W2, __half* __restrict__ W2f) {
    __shared__ float tile[32][33];
    const int z = blockIdx.z;
    const int C = z ? O_ : H_;
    if (blockIdx.x * 32 >= C) return;
    const float* in = z ? W2 : W1;
    __half* outH    = z ? W2f : W1f;
    int c0 = blockIdx.x * 32, r0 = blockIdx.y * 32;
    int x = threadIdx.x, y = threadIdx.y;
    #pragma unroll
    for (int i = 0; i < 32; i += 8)
        tile[y + i][x] = in[(size_t)(r0 + y + i) * C + c0 + x];
    __syncthreads();
    #pragma unroll
    for (int i = 0; i < 32; i += 8) {
        float v = tile[x][y + i];
        outH[(size_t)(c0 + y + i) * KDIM + r0 + x] = __float2half_rn(v);
    }
}

// ---------------------------------------------------------------------------
// GEMM via fp16 mma.sync, BK=64, 3-stage cp.async pipeline, XOR-swizzled smem,
// B-fragments hoisted per chunk.
// MODE 1: Hf   = relu(concat(X[:,t-1],X[:,t]) @ W1 + b1)   [128000 x 256]
// MODE 2: actH = activation(h @ W2 + b2)                   [128000 x 512]
// ---------------------------------------------------------------------------
template<int MODE>
__global__ __launch_bounds__(256, 2) void gemm_mma(const float* __restrict__ bias) {
    extern __shared__ __align__(128) char sm[];
    const int tid = threadIdx.x;
    const int lane = tid & 31;
    const int wid = tid >> 5;
    const int wm = wid >> 2;
    const int wn = wid & 3;
    const int n0 = blockIdx.x * BN;
    const int m0 = blockIdx.y * BM;

    const uint32_t smbase = smem_u32(sm);

    // staging: thread item p -> row = (tid>>3) + 32p, chunk k = tid&7
    const int st_row = tid >> 3;            // 0..31
    const int st_k   = tid & 7;             // 16B chunk in row
    const uint32_t st_sw = (uint32_t)(st_row & 7);
    const uint32_t st_d0 = (uint32_t)st_row * ROWB + (((uint32_t)st_k ^ st_sw) << 4);

    const __half* AF = (MODE == 1) ? g_Xf : g_Hf;
    const __half* WF = (MODE == 1) ? g_W1f : g_W2f;

    size_t acur[4], aprev[4], boff[4];
    #pragma unroll
    for (int p = 0; p < 4; p++) {
        int row = st_row + 32 * p;
        if (MODE == 1) {
            int gr = m0 + row;
            int b = gr / T_;
            int t = gr - b * T_;
            int tp = t ? (t - 1) : 0;
            acur[p]  = ((size_t)b * T_ + t)  * F_ + st_k * 8;
            aprev[p] = ((size_t)b * T_ + tp) * F_ + st_k * 8;
        } else {
            acur[p] = (size_t)(m0 + row) * H_ + st_k * 8;
        }
        boff[p] = (size_t)(n0 + row) * KDIM + st_k * 8;
    }

    auto stage = [&](int c, int slot) {
        const int k0 = c * BK;
        uint32_t sA = smbase + slot * SSTR;
        #pragma unroll
        for (int p = 0; p < 4; p++) {
            uint32_t d = st_d0 + p * (32 * ROWB);
            size_t so;
            if (MODE == 1) so = (k0 < 128) ? (aprev[p] + k0) : (acur[p] + (k0 - 128));
            else           so = acur[p] + k0;
            cp16(sA + d,      AF + so);
            cp16(sA + PL + d, WF + boff[p] + k0);
        }
    };

    float acc[4][4][4];
    #pragma unroll
    for (int i = 0; i < 4; i++)
        #pragma unroll
        for (int j = 0; j < 4; j++)
            #pragma unroll
            for (int q = 0; q < 4; q++) acc[i][j][q] = 0.f;

    // ldmatrix addressing: all row offsets are multiples of 8 -> (row&7) const
    const uint32_t a_rowb = (uint32_t)(wm * 64) + (lane & 15);
    const uint32_t a_half = (uint32_t)lane >> 4;                 // 0/1
    const uint32_t b_rowb = (uint32_t)(wn * 32) + (((uint32_t)lane >> 4) << 3) + (lane & 7);
    const uint32_t b_half = ((uint32_t)lane >> 3) & 1;
    const uint32_t sw_a   = a_rowb & 7;
    const uint32_t sw_b   = b_rowb & 7;

    stage(0, 0); CP_COMMIT();
    stage(1, 1); CP_COMMIT();

    #pragma unroll 1
    for (int c = 0; c < NKC; c++) {
        CP_WAIT1();                  // group c complete (c+1 may be in flight)
        __syncthreads();             // all warps done reading slot (c-1)%3
        if (c + 2 < NKC) stage(c + 2, (c + 2) % NSTAGE);
        CP_COMMIT();

        const int slot = c % NSTAGE;
        const uint32_t sA = smbase + slot * SSTR;
        const uint32_t sB = sA + PL;

        // Hoist all B fragments for this chunk: 8 independent LDSM
        uint32_t bfall[4][4][2];
        #pragma unroll
        for (int s = 0; s < 4; s++) {
            const uint32_t b_co = ((2 * s + b_half) ^ sw_b) << 4;
            #pragma unroll
            for (int jj = 0; jj < 2; jj++) {
                uint32_t off = (b_rowb + jj * 16) * ROWB + b_co;
                uint32_t r0, r1, r2, r3;
                ldsm_x4(r0, r1, r2, r3, sB + off);
                bfall[s][2 * jj][0] = r0;     bfall[s][2 * jj][1] = r1;
                bfall[s][2 * jj + 1][0] = r2; bfall[s][2 * jj + 1][1] = r3;
            }
        }

        #pragma unroll
        for (int s = 0; s < 4; s++) {
            const uint32_t a_co = ((2 * s + a_half) ^ sw_a) << 4;
            #pragma unroll
            for (int i = 0; i < 4; i++) {
                uint32_t off = (a_rowb + i * 16) * ROWB + a_co;
                uint32_t af[4];
                ldsm_x4(af[0], af[1], af[2], af[3], sA + off);
                #pragma unroll
                for (int j = 0; j < 4; j++)
                    mma_fp16(acc[i][j], af, bfall[s][j]);
            }
        }
    }

    // ---- epilogue ----
    const int rloc = lane >> 2;
    const int cpair = (lane & 3) * 2;
    #pragma unroll
    for (int i = 0; i < 4; i++) {
        int r0 = m0 + wm * 64 + i * 16 + rloc;
        int r1 = r0 + 8;
        #pragma unroll
        for (int j = 0; j < 4; j++) {
            int ng = n0 + wn * 32 + j * 8 + cpair;
            float2 bb = *(const float2*)&bias[ng];
            float u0 = acc[i][j][0] + bb.x, u1 = acc[i][j][1] + bb.y;
            float u2 = acc[i][j][2] + bb.x, u3 = acc[i][j][3] + bb.y;
            if (MODE == 1) {
                u0 = fmaxf(u0, 0.f); u1 = fmaxf(u1, 0.f);
                u2 = fmaxf(u2, 0.f); u3 = fmaxf(u3, 0.f);
                *(uint32_t*)&g_Hf[(size_t)r0 * H_ + ng] = pack_h2(u0, u1);
                *(uint32_t*)&g_Hf[(size_t)r1 * H_ + ng] = pack_h2(u2, u3);
            } else {
                bool sp = (blockIdx.x == 2);   // cols [256,384): softplus (delta)
                float uu[4] = {u0, u1, u2, u3};
                float v[4];
                #pragma unroll
                for (int q = 0; q < 4; q++) {
                    float u = uu[q];
                    v[q] = sp ? (__logf(1.f + __expf(-fabsf(u))) + fmaxf(u, 0.f))
                              : sigmoid_tanh(u);
                }
                *(uint32_t*)&g_actH[(size_t)r0 * O_ + ng] = pack_h2(v[0], v[1]);
                *(uint32_t*)&g_actH[(size_t)r1 * O_ + ng] = pack_h2(v[2], v[3]);
            }
        }
    }
}

// ---------------------------------------------------------------------------
// Scan stage A: per-chunk composition  (writes [b][c][f], fully coalesced)
// ---------------------------------------------------------------------------
__global__ __launch_bounds__(256) void scan_reduce_kernel() {
    int id = blockIdx.x * blockDim.x + threadIdx.x;
    int f = id & (F_ - 1);
    int r = id >> 7;
    int c = r % NC;
    int b = r / NC;

    const __half* actb = g_actH + (size_t)(b * T_) * O_;
    const __half* Xfb  = g_Xf + (size_t)b * T_ * F_;

    float A = 1.f, Bv = 0.f;
    int t0 = c * CHUNK;
    #pragma unroll 4
    for (int t = t0; t < t0 + CHUNK; t++) {
        float s = __half2float(actb[(size_t)t * O_ + f]);
        float x = __half2float(Xfb[(size_t)t * F_ + f]);
        float a = 1.f - s;
        A  *= a;
        Bv = a * Bv + s * x;
    }
    g_Ac[id] = A;
    g_Bc[id] = Bv;
}

// ---------------------------------------------------------------------------
// Scan stage B: per-(b,f) chain over NC chunk summaries, smem-cached.
// ---------------------------------------------------------------------------
__global__ __launch_bounds__(128) void scan_chain_kernel() {
    extern __shared__ float chsm[];              // As[NC*F_], Bs[NC*F_]
    float* As = chsm;
    float* Bs = chsm + NC * F_;
    int b = blockIdx.x, f = threadIdx.x;
    int base = b * NC * F_;

    for (int i = f; i < NC * F_; i += 128) {
        As[i] = g_Ac[base + i];
        Bs[i] = g_Bc[base + i];
    }
    __syncthreads();

    float M = 0.f;
    #pragma unroll 5
    for (int c = 0; c < NC; c++) {
        g_Ms[base + c * F_ + f] = M;
        M = As[c * F_ + f] * M + Bs[c * F_ + f];
    }
}

// ---------------------------------------------------------------------------
// Scan stage C: replay + PCEN epilogue; one 32x128 transpose tile per CTA.
// grid = B_*NC = 4000 blocks, 128 threads = f
// ---------------------------------------------------------------------------
__global__ __launch_bounds__(128) void scan_final_kernel(float* __restrict__ out) {
    __shared__ float tile[32][129];
    int bc = blockIdx.x;
    int b = bc / NC;
    int c = bc % NC;
    int f = threadIdx.x;
    int lane = f & 31, wid = f >> 5;

    const __half* actb = g_actH + (size_t)(b * T_) * O_;
    const __half* Xfb  = g_Xf + (size_t)b * T_ * F_;

    float M = g_Ms[(b * NC + c) * F_ + f];
    int t0 = c * CHUNK;
    #pragma unroll 4
    for (int q = 0; q < CHUNK; q++) {
        int t = t0 + q;
        const __half* rowp = actb + (size_t)t * O_;
        float s     = __half2float(rowp[f]);
        float alpha = __half2float(rowp[128 + f]);
        float delta = __half2float(rowp[256 + f]);
        float r     = __half2float(rowp[384 + f]);
        float x = __half2float(Xfb[(size_t)t * F_ + f]);
        M = (1.f - s) * M + s * x;
        float base = x * __powf(M + EPS, -alpha) + delta;
        tile[q][f] = __powf(base, r) - __powf(delta, r);
    }
    __syncthreads();
    #pragma unroll
    for (int ff = wid; ff < 128; ff += 4)
        out[(size_t)(b * F_ + ff) * T_ + t0 + lane] = tile[lane][ff];
}

// ---------------------------------------------------------------------------
// Launch
// ---------------------------------------------------------------------------
extern "C" void kernel_launch(void* const* d_in, const int* in_sizes, int n_in,
                              void* d_out, int out_size) {
    const float* X  = (const float*)d_in[0];
    const float* W1 = (const float*)d_in[1];
    const float* b1 = (const float*)d_in[2];
    const float* W2 = (const float*)d_in[3];
    const float* b2 = (const float*)d_in[4];
    float* out = (float*)d_out;

    __half *Xf, *W1f, *W2f;
    cudaGetSymbolAddress((void**)&Xf,  g_Xf);
    cudaGetSymbolAddress((void**)&W1f, g_W1f);
    cudaGetSymbolAddress((void**)&W2f, g_W2f);

    // Idempotent host-side attribute sets (no stream interaction; capture-safe)
    cudaFuncSetAttribute(gemm_mma<1>, cudaFuncAttributeMaxDynamicSharedMemorySize, SMEM_GEMM);
    cudaFuncSetAttribute(gemm_mma<2>, cudaFuncAttributeMaxDynamicSharedMemorySize, SMEM_GEMM);
    cudaFuncSetAttribute(scan_chain_kernel, cudaFuncAttributeMaxDynamicSharedMemorySize, CHAIN_SMEM);

    // X [F][T] per batch -> Xf(fp16) [T][F]; W1 -> [H][K] and W2 -> [O][K] in one launch
    transpose_conv<<<dim3(T_ / 32, F_ / 32, B_), dim3(32, 8)>>>(X, Xf, F_, T_);
    transpose_w<<<dim3(O_ / 32, KDIM / 32, 2), dim3(32, 8)>>>(W1, W1f, W2, W2f);

    gemm_mma<1><<<dim3(H_ / BN, (B_ * T_) / BM), 256, SMEM_GEMM>>>(b1);   // (2, 1000)
    gemm_mma<2><<<dim3(O_ / BN, (B_ * T_) / BM), 256, SMEM_GEMM>>>(b2);   // (4, 1000)

    scan_reduce_kernel<<<(B_ * NC * F_) / 256, 256>>>();
    scan_chain_kernel<<<B_, 128, CHAIN_SMEM>>>();
    scan_final_kernel<<<B_ * NC, 128>>>(out);
}

// round 15
// speedup vs baseline: 1.5525x; 1.0334x over previous
#include <cuda_runtime.h>
#include <cuda_fp16.h>
#include <math.h>
#include <stdint.h>

// Problem constants
#define B_   32
#define F_   128
#define T_   4000
#define H_   256     // hidden
#define O_   512     // 4F
#define KDIM 256     // 2F
#define EPS  1e-6f

// Scan chunking: 125 chunks of 32 -> 4000
#define CHUNK 32
#define NC    125
#define CHAIN_SMEM (NC * F_ * 2 * 4)   // 128000 B

// Fused MLP kernel geometry
#define SLOT_BYTES 49152              // phase1 stage: A 16KB + B 32KB
#define H_OFF      147456             // h panels after 3 stage slots
#define SMEM_FUSED (H_OFF + 65536)    // 212992 B (208 KB)

// ---------------------------------------------------------------------------
// Scratch (device globals)
// ---------------------------------------------------------------------------
__device__ __align__(128) __half  g_Xf  [B_ * T_ * F_];   // fp16 [b][t][f] (GEMM1 + scans)
__device__ __align__(128) __half  g_W1f [H_ * KDIM];
__device__ __align__(128) __half  g_W2f [O_ * KDIM];
__device__ __align__(128) __half  g_actH[B_ * T_ * O_];   // fp16 activations
__device__ float g_Ac[B_ * NC * F_];    // [b][c][f]
__device__ float g_Bc[B_ * NC * F_];
__device__ float g_Ms[B_ * NC * F_];

// ---------------------------------------------------------------------------
// Helpers
// ---------------------------------------------------------------------------
__device__ __forceinline__ uint32_t smem_u32(const void* p) {
    uint32_t a;
    asm("{ .reg .u64 t; cvta.to.shared.u64 t, %1; cvt.u32.u64 %0, t; }" : "=r"(a) : "l"(p));
    return a;
}
__device__ __forceinline__ void cp16(uint32_t dst, const void* src) {
    asm volatile("cp.async.cg.shared.global [%0], [%1], 16;" :: "r"(dst), "l"(src) : "memory");
}
#define CP_COMMIT() asm volatile("cp.async.commit_group;" ::: "memory")
#define CP_WAIT1()  asm volatile("cp.async.wait_group 1;" ::: "memory")

__device__ __forceinline__ void ldsm_x4(uint32_t& r0, uint32_t& r1, uint32_t& r2, uint32_t& r3,
                                        uint32_t addr) {
    asm volatile("ldmatrix.sync.aligned.m8n8.x4.shared.b16 {%0,%1,%2,%3}, [%4];"
                 : "=r"(r0), "=r"(r1), "=r"(r2), "=r"(r3) : "r"(addr));
}
__device__ __forceinline__ void mma_fp16(float* c, const uint32_t* a, const uint32_t* b) {
    asm volatile("mma.sync.aligned.m16n8k16.row.col.f32.f16.f16.f32 "
                 "{%0,%1,%2,%3}, {%4,%5,%6,%7}, {%8,%9}, {%0,%1,%2,%3};"
                 : "+f"(c[0]), "+f"(c[1]), "+f"(c[2]), "+f"(c[3])
                 : "r"(a[0]), "r"(a[1]), "r"(a[2]), "r"(a[3]), "r"(b[0]), "r"(b[1]));
}
__device__ __forceinline__ uint32_t pack_h2(float x, float y) {
    __half2 h = __floats2half2_rn(x, y);
    return *(uint32_t*)&h;
}
// sigmoid via MUFU.TANH: 1 MUFU + 2 FMA
__device__ __forceinline__ float sigmoid_tanh(float x) {
    float t;
    asm("tanh.approx.f32 %0, %1;" : "=f"(t) : "f"(x * 0.5f));
    return fmaf(t, 0.5f, 0.5f);
}

// ---------------------------------------------------------------------------
// Transpose + fp16 convert: in [R][C] fp32 -> out [C][R] fp16  (X path)
// ---------------------------------------------------------------------------
__global__ void transpose_conv(const float* __restrict__ in, __half* __restrict__ outH,
                               int R, int C) {
    __shared__ float tile[32][33];
    size_t boff = (size_t)blockIdx.z * R * C;
    in += boff;
    int c0 = blockIdx.x * 32, r0 = blockIdx.y * 32;
    int x = threadIdx.x, y = threadIdx.y;
    #pragma unroll
    for (int i = 0; i < 32; i += 8)
        tile[y + i][x] = in[(size_t)(r0 + y + i) * C + c0 + x];
    __syncthreads();
    #pragma unroll
    for (int i = 0; i < 32; i += 8) {
        float v = tile[x][y + i];
        outH[boff + (size_t)(c0 + y + i) * R + r0 + x] = __float2half_rn(v);
    }
}

// ---------------------------------------------------------------------------
// Merged W1+W2 transpose: z=0 -> W1 [K][H]->[H][K], z=1 -> W2 [K][O]->[O][K]
// ---------------------------------------------------------------------------
__global__ void transpose_w(const float* __restrict__ W1, __half* __restrict__ W1f,
                            const float* __restrict__ W2, __half* __restrict__ W2f) {
    __shared__ float tile[32][33];
    const int z = blockIdx.z;
    const int C = z ? O_ : H_;
    if (blockIdx.x * 32 >= C) return;
    const float* in = z ? W2 : W1;
    __half* outH    = z ? W2f : W1f;
    int c0 = blockIdx.x * 32, r0 = blockIdx.y * 32;
    int x = threadIdx.x, y = threadIdx.y;
    #pragma unroll
    for (int i = 0; i < 32; i += 8)
        tile[y + i][x] = in[(size_t)(r0 + y + i) * C + c0 + x];
    __syncthreads();
    #pragma unroll
    for (int i = 0; i < 32; i += 8) {
        float v = tile[x][y + i];
        outH[(size_t)(c0 + y + i) * KDIM + r0 + x] = __float2half_rn(v);
    }
}

// ---------------------------------------------------------------------------
// Fused MLP: one CTA per 128 rows (m0 = blockIdx.x*128), 512 threads.
// Phase 1: h(128x256) = relu(concat(X[:,t-1],X[:,t]) @ W1 + b1)  -> SMEM (fp16)
// Phase 2: actH(128x512) = activation(h @ W2 + b2)               -> global
// smem: 3 stage slots (48KB each) reused by phase2 W2 buffers (2x64KB),
//       h panels at H_OFF (4 panels x 16KB).
// ---------------------------------------------------------------------------
__global__ __launch_bounds__(512, 1) void fused_mlp(const float* __restrict__ b1,
                                                    const float* __restrict__ b2) {
    extern __shared__ __align__(128) char sm[];
    const int tid = threadIdx.x;
    const int lane = tid & 31;
    const int wid = tid >> 5;          // 0..15
    const int wm = wid >> 2;           // 0..3 (M blocks of 32)
    const int wn = wid & 3;            // 0..3
    const int m0 = blockIdx.x * 128;
    const uint32_t base = smem_u32(sm);

    // staging: st_row 0..63, st_k 0..7 (16B chunks); swizzle const per thread
    const int st_row = tid >> 3;
    const int st_k   = tid & 7;
    const uint32_t st_off = (uint32_t)st_row * 128 + (((uint32_t)st_k ^ (uint32_t)(st_row & 7)) << 4);

    size_t acur[2], aprev[2];
    #pragma unroll
    for (int p = 0; p < 2; p++) {
        int gr = m0 + st_row + 64 * p;
        int b = gr / T_;
        int t = gr - b * T_;
        int tp = t ? t - 1 : 0;
        acur[p]  = ((size_t)b * T_ + t)  * F_ + st_k * 8;
        aprev[p] = ((size_t)b * T_ + tp) * F_ + st_k * 8;
    }

    auto stage1 = [&](int c, int slot) {
        uint32_t sA = base + slot * SLOT_BYTES;
        const int k0 = c * 64;
        #pragma unroll
        for (int p = 0; p < 2; p++) {
            size_t so = (c < 2) ? (aprev[p] + k0) : (acur[p] + (k0 - 128));
            cp16(sA + st_off + p * 8192, g_Xf + so);
        }
        #pragma unroll
        for (int p = 0; p < 4; p++)
            cp16(sA + 16384 + st_off + p * 8192,
                 g_W1f + (size_t)(st_row + 64 * p) * KDIM + k0 + st_k * 8);
    };

    auto stage2 = [&](int nc, uint32_t buf) {
        #pragma unroll
        for (int kk = 0; kk < 4; kk++)
            #pragma unroll
            for (int p = 0; p < 2; p++)
                cp16(buf + kk * 16384 + st_off + p * 8192,
                     g_W2f + (size_t)(nc * 128 + st_row + 64 * p) * KDIM + kk * 64 + st_k * 8);
    };

    // ldmatrix addressing (all row offsets multiples of 8 -> row&7 const per thread)
    const uint32_t a_rowb  = (uint32_t)(wm * 32) + (lane & 15);
    const uint32_t a_half  = (uint32_t)lane >> 4;
    const uint32_t sw_a    = a_rowb & 7;
    const uint32_t b1_rowb = (uint32_t)(wn * 64) + (((uint32_t)lane >> 4) << 3) + (lane & 7);
    const uint32_t b2_rowb = (uint32_t)(wn * 32) + (((uint32_t)lane >> 4) << 3) + (lane & 7);
    const uint32_t b_half  = ((uint32_t)lane >> 3) & 1;
    const uint32_t sw_b1   = b1_rowb & 7;
    const uint32_t sw_b2   = b2_rowb & 7;
    const int rloc  = lane >> 2;
    const int cpair = (lane & 3) * 2;

    // ---------------- Phase 1: h = relu(Xcat @ W1 + b1) ----------------
    float acc1[2][8][4];
    #pragma unroll
    for (int i = 0; i < 2; i++)
        #pragma unroll
        for (int j = 0; j < 8; j++)
            #pragma unroll
            for (int q = 0; q < 4; q++) acc1[i][j][q] = 0.f;

    stage1(0, 0); CP_COMMIT();
    stage1(1, 1); CP_COMMIT();

    #pragma unroll 1
    for (int c = 0; c < 4; c++) {
        CP_WAIT1();
        __syncthreads();
        if (c + 2 < 4) stage1(c + 2, (c + 2) % 3);
        CP_COMMIT();

        const uint32_t sA = base + (c % 3) * SLOT_BYTES;
        const uint32_t sB = sA + 16384;
        #pragma unroll
        for (int s = 0; s < 4; s++) {
            const uint32_t a_co = ((2 * s + a_half) ^ sw_a) << 4;
            const uint32_t b_co = ((2 * s + b_half) ^ sw_b1) << 4;
            uint32_t bf[8][2];
            #pragma unroll
            for (int jj = 0; jj < 4; jj++) {
                uint32_t r0, r1, r2, r3;
                ldsm_x4(r0, r1, r2, r3, sB + (b1_rowb + jj * 16) * 128 + b_co);
                bf[2 * jj][0] = r0;     bf[2 * jj][1] = r1;
                bf[2 * jj + 1][0] = r2; bf[2 * jj + 1][1] = r3;
            }
            #pragma unroll
            for (int i = 0; i < 2; i++) {
                uint32_t af[4];
                ldsm_x4(af[0], af[1], af[2], af[3], sA + (a_rowb + i * 16) * 128 + a_co);
                #pragma unroll
                for (int j = 0; j < 8; j++)
                    mma_fp16(acc1[i][j], af, bf[j]);
            }
        }
    }

    // epilogue: bias + relu + fp16 -> h smem panels (swizzled)
    #pragma unroll
    for (int i = 0; i < 2; i++) {
        int r0 = wm * 32 + i * 16 + rloc;
        #pragma unroll
        for (int j = 0; j < 8; j++) {
            int ng = wn * 64 + j * 8 + cpair;
            float2 bb = *(const float2*)&b1[ng];
            float u0 = fmaxf(acc1[i][j][0] + bb.x, 0.f);
            float u1 = fmaxf(acc1[i][j][1] + bb.y, 0.f);
            float u2 = fmaxf(acc1[i][j][2] + bb.x, 0.f);
            float u3 = fmaxf(acc1[i][j][3] + bb.y, 0.f);
            int panel = ng >> 6, cp = ng & 63;
            uint32_t o0 = H_OFF + panel * 16384 + (uint32_t)r0 * 128
                        + (((uint32_t)(cp >> 3) ^ (uint32_t)(r0 & 7)) << 4) + (uint32_t)(cp & 7) * 2;
            *(uint32_t*)(sm + o0)            = pack_h2(u0, u1);
            *(uint32_t*)(sm + o0 + 8 * 128)  = pack_h2(u2, u3);   // row r0+8: same swizzle
        }
    }
    __syncthreads();

    // ---------------- Phase 2: actH = activation(h @ W2 + b2) ----------------
    stage2(0, base);          CP_COMMIT();
    stage2(1, base + 65536);  CP_COMMIT();

    #pragma unroll 1
    for (int nc = 0; nc < 4; nc++) {
        CP_WAIT1();
        __syncthreads();
        const uint32_t bbuf = base + (uint32_t)(nc & 1) * 65536;

        float acc2[2][4][4];
        #pragma unroll
        for (int i = 0; i < 2; i++)
            #pragma unroll
            for (int j = 0; j < 4; j++)
                #pragma unroll
                for (int q = 0; q < 4; q++) acc2[i][j][q] = 0.f;

        #pragma unroll
        for (int kk = 0; kk < 4; kk++) {
            const uint32_t hA = base + H_OFF + kk * 16384;
            const uint32_t sB = bbuf + kk * 16384;
            #pragma unroll
            for (int s = 0; s < 4; s++) {
                const uint32_t a_co = ((2 * s + a_half) ^ sw_a) << 4;
                const uint32_t b_co = ((2 * s + b_half) ^ sw_b2) << 4;
                uint32_t bf[4][2];
                #pragma unroll
                for (int jj = 0; jj < 2; jj++) {
                    uint32_t r0, r1, r2, r3;
                    ldsm_x4(r0, r1, r2, r3, sB + (b2_rowb + jj * 16) * 128 + b_co);
                    bf[2 * jj][0] = r0;     bf[2 * jj][1] = r1;
                    bf[2 * jj + 1][0] = r2; bf[2 * jj + 1][1] = r3;
                }
                #pragma unroll
                for (int i = 0; i < 2; i++) {
                    uint32_t af[4];
                    ldsm_x4(af[0], af[1], af[2], af[3], hA + (a_rowb + i * 16) * 128 + a_co);
                    #pragma unroll
                    for (int j = 0; j < 4; j++)
                        mma_fp16(acc2[i][j], af, bf[j]);
                }
            }
        }

        // epilogue: bias + activation -> actH
        const bool sp = (nc == 2);   // cols [256,384): softplus (delta)
        #pragma unroll
        for (int i = 0; i < 2; i++) {
            int r0 = m0 + wm * 32 + i * 16 + rloc;
            int r1 = r0 + 8;
            #pragma unroll
            for (int j = 0; j < 4; j++) {
                int ng = nc * 128 + wn * 32 + j * 8 + cpair;
                float2 bb = *(const float2*)&b2[ng];
                float uu[4] = {acc2[i][j][0] + bb.x, acc2[i][j][1] + bb.y,
                               acc2[i][j][2] + bb.x, acc2[i][j][3] + bb.y};
                float v[4];
                #pragma unroll
                for (int q = 0; q < 4; q++) {
                    float u = uu[q];
                    v[q] = sp ? (__logf(1.f + __expf(-fabsf(u))) + fmaxf(u, 0.f))
                              : sigmoid_tanh(u);
                }
                *(uint32_t*)&g_actH[(size_t)r0 * O_ + ng] = pack_h2(v[0], v[1]);
                *(uint32_t*)&g_actH[(size_t)r1 * O_ + ng] = pack_h2(v[2], v[3]);
            }
        }
        __syncthreads();
        if (nc + 2 < 4) stage2(nc + 2, bbuf);
        CP_COMMIT();   // unconditional: keeps wait_group 1 semantics valid at nc=3
    }
}

// ---------------------------------------------------------------------------
// Scan stage A: per-chunk composition  (writes [b][c][f], fully coalesced)
// ---------------------------------------------------------------------------
__global__ __launch_bounds__(256) void scan_reduce_kernel() {
    int id = blockIdx.x * blockDim.x + threadIdx.x;
    int f = id & (F_ - 1);
    int r = id >> 7;
    int c = r % NC;
    int b = r / NC;

    const __half* actb = g_actH + (size_t)(b * T_) * O_;
    const __half* Xfb  = g_Xf + (size_t)b * T_ * F_;

    float A = 1.f, Bv = 0.f;
    int t0 = c * CHUNK;
    #pragma unroll 4
    for (int t = t0; t < t0 + CHUNK; t++) {
        float s = __half2float(actb[(size_t)t * O_ + f]);
        float x = __half2float(Xfb[(size_t)t * F_ + f]);
        float a = 1.f - s;
        A  *= a;
        Bv = a * Bv + s * x;
    }
    g_Ac[id] = A;
    g_Bc[id] = Bv;
}

// ---------------------------------------------------------------------------
// Scan stage B: per-(b,f) chain over NC chunk summaries, smem-cached.
// ---------------------------------------------------------------------------
__global__ __launch_bounds__(128) void scan_chain_kernel() {
    extern __shared__ float chsm[];              // As[NC*F_], Bs[NC*F_]
    float* As = chsm;
    float* Bs = chsm + NC * F_;
    int b = blockIdx.x, f = threadIdx.x;
    int base = b * NC * F_;

    for (int i = f; i < NC * F_; i += 128) {
        As[i] = g_Ac[base + i];
        Bs[i] = g_Bc[base + i];
    }
    __syncthreads();

    float M = 0.f;
    #pragma unroll 5
    for (int c = 0; c < NC; c++) {
        g_Ms[base + c * F_ + f] = M;
        M = As[c * F_ + f] * M + Bs[c * F_ + f];
    }
}

// ---------------------------------------------------------------------------
// Scan stage C: replay + PCEN epilogue; one 32x128 transpose tile per CTA.
// ---------------------------------------------------------------------------
__global__ __launch_bounds__(128) void scan_final_kernel(float* __restrict__ out) {
    __shared__ float tile[32][129];
    int bc = blockIdx.x;
    int b = bc / NC;
    int c = bc % NC;
    int f = threadIdx.x;
    int lane = f & 31, wid = f >> 5;

    const __half* actb = g_actH + (size_t)(b * T_) * O_;
    const __half* Xfb  = g_Xf + (size_t)b * T_ * F_;

    float M = g_Ms[(b * NC + c) * F_ + f];
    int t0 = c * CHUNK;
    #pragma unroll 4
    for (int q = 0; q < CHUNK; q++) {
        int t = t0 + q;
        const __half* rowp = actb + (size_t)t * O_;
        float s     = __half2float(rowp[f]);
        float alpha = __half2float(rowp[128 + f]);
        float delta = __half2float(rowp[256 + f]);
        float r     = __half2float(rowp[384 + f]);
        float x = __half2float(Xfb[(size_t)t * F_ + f]);
        M = (1.f - s) * M + s * x;
        float base = x * __powf(M + EPS, -alpha) + delta;
        tile[q][f] = __powf(base, r) - __powf(delta, r);
    }
    __syncthreads();
    #pragma unroll
    for (int ff = wid; ff < 128; ff += 4)
        out[(size_t)(b * F_ + ff) * T_ + t0 + lane] = tile[lane][ff];
}

// ---------------------------------------------------------------------------
// Launch
// ---------------------------------------------------------------------------
extern "C" void kernel_launch(void* const* d_in, const int* in_sizes, int n_in,
                              void* d_out, int out_size) {
    const float* X  = (const float*)d_in[0];
    const float* W1 = (const float*)d_in[1];
    const float* b1 = (const float*)d_in[2];
    const float* W2 = (const float*)d_in[3];
    const float* b2 = (const float*)d_in[4];
    float* out = (float*)d_out;

    __half *Xf, *W1f, *W2f;
    cudaGetSymbolAddress((void**)&Xf,  g_Xf);
    cudaGetSymbolAddress((void**)&W1f, g_W1f);
    cudaGetSymbolAddress((void**)&W2f, g_W2f);

    // Idempotent host-side attribute sets (no stream interaction; capture-safe)
    cudaFuncSetAttribute(fused_mlp, cudaFuncAttributeMaxDynamicSharedMemorySize, SMEM_FUSED);
    cudaFuncSetAttribute(scan_chain_kernel, cudaFuncAttributeMaxDynamicSharedMemorySize, CHAIN_SMEM);

    // X [F][T] per batch -> Xf(fp16) [T][F]; W1 -> [H][K] and W2 -> [O][K] in one launch
    transpose_conv<<<dim3(T_ / 32, F_ / 32, B_), dim3(32, 8)>>>(X, Xf, F_, T_);
    transpose_w<<<dim3(O_ / 32, KDIM / 32, 2), dim3(32, 8)>>>(W1, W1f, W2, W2f);

    fused_mlp<<<(B_ * T_) / 128, 512, SMEM_FUSED>>>(b1, b2);   // 1000 CTAs

    scan_reduce_kernel<<<(B_ * NC * F_) / 256, 256>>>();
    scan_chain_kernel<<<B_, 128, CHAIN_SMEM>>>();
    scan_final_kernel<<<B_ * NC, 128>>>(out);
}